// round 1
// baseline (speedup 1.0000x reference)
#include <cuda_runtime.h>
#include <math.h>

// Problem constants (fixed instance)
#define RR   4
#define NN   20000     // destination / output nodes
#define NSRC 20000
#define DD   256
#define EE   640000
#define KK   16
#define CAP  128       // max edges per (relation, dst) bucket; Poisson(32) tail -> safe

// Static scratch (allocation-free rule: __device__ globals)
__device__ int   g_cnt[RR * NN];
__device__ int   g_slots[(size_t)RR * NN * CAP];   // stores src index per edge slot
__device__ float g_H[(size_t)NN * RR * DD];        // H laid out [N][R][D]

// ---------------------------------------------------------------------------
__global__ void zero_cnt_kernel() {
    int i = blockIdx.x * blockDim.x + threadIdx.x;
    if (i < RR * NN) g_cnt[i] = 0;
}

// Count edges per (r, dst) and drop the src index into a bucket slot.
__global__ void bucket_kernel(const int* __restrict__ src_idx,
                              const int* __restrict__ dst_idx) {
    int idx = blockIdx.x * blockDim.x + threadIdx.x;
    if (idx >= RR * EE) return;
    int r   = idx / EE;
    int dst = dst_idx[idx];
    int src = src_idx[idx];
    int b   = r * NN + dst;
    int rank = atomicAdd(&g_cnt[b], 1);
    if (rank < CAP) g_slots[(size_t)b * CAP + rank] = src;
}

// ---------------------------------------------------------------------------
// One block per (r, n). Computes segment softmax over this node's edges
// (selected branch only) and the weighted sum of x rows -> g_H[n][r][:].
__global__ __launch_bounds__(256) void agg_kernel(
    const float* __restrict__ x,    // [R, NSRC, D]
    const float* __restrict__ d,    // [R, NSRC]
    const float* __restrict__ d1,
    const float* __restrict__ d2,
    const int*   __restrict__ split_p)
{
    const int b = blockIdx.x;
    const int r = b / NN;
    const int n = b - r * NN;
    const int t = threadIdx.x;

    __shared__ int   ssrc[CAP];
    __shared__ float sw[CAP];     // logits -> exp -> normalized weights
    __shared__ float red[8];

    int cnt = g_cnt[b];
    if (cnt > CAP) cnt = CAP;

    const int split = split_p ? __ldg(split_p) : 10000;
    const bool use1 = (n < split);

    // Fill srcs + logits
    for (int i = t; i < cnt; i += 256) {
        int s = g_slots[(size_t)b * CAP + i];
        ssrc[i] = s;
        float dv = d[r * NSRC + s];
        float l  = use1 ? (d1[r * NSRC + s] / dv)
                        : (-d2[r * NSRC + s] / dv);
        sw[i] = l;
    }
    __syncthreads();

    const int lane = t & 31, w = t >> 5;

    // max over logits (cnt <= 128 < 256: one value per thread)
    float v = (t < cnt) ? sw[t] : -1e30f;
    #pragma unroll
    for (int o = 16; o; o >>= 1) v = fmaxf(v, __shfl_xor_sync(0xffffffffu, v, o));
    if (lane == 0) red[w] = v;
    __syncthreads();
    if (t == 0) {
        float m = red[0];
        #pragma unroll
        for (int i = 1; i < 8; i++) m = fmaxf(m, red[i]);
        red[0] = m;
    }
    __syncthreads();
    const float m = red[0];

    float e = (t < cnt) ? expf(sw[t] - m) : 0.f;
    if (t < cnt) sw[t] = e;
    float sv = e;
    #pragma unroll
    for (int o = 16; o; o >>= 1) sv += __shfl_xor_sync(0xffffffffu, sv, o);
    __syncthreads();              // everyone has read red[0] (m) before overwrite
    if (lane == 0) red[w] = sv;
    __syncthreads();
    if (t == 0) {
        float s = 0.f;
        #pragma unroll
        for (int i = 0; i < 8; i++) s += red[i];
        red[0] = 1.f / fmaxf(s, 1e-9f);
    }
    __syncthreads();
    const float winv = red[0];
    if (t < cnt) sw[t] *= winv;
    __syncthreads();

    // Weighted gather-sum: thread t owns column t.
    const float* xr = x + (size_t)r * NSRC * DD + t;
    float acc = 0.f;
    int i = 0;
    for (; i + 4 <= cnt; i += 4) {
        float w0 = sw[i], w1 = sw[i + 1], w2 = sw[i + 2], w3 = sw[i + 3];
        const float* p0 = xr + (size_t)ssrc[i]     * DD;
        const float* p1 = xr + (size_t)ssrc[i + 1] * DD;
        const float* p2 = xr + (size_t)ssrc[i + 2] * DD;
        const float* p3 = xr + (size_t)ssrc[i + 3] * DD;
        acc += w0 * p0[0];
        acc += w1 * p1[0];
        acc += w2 * p2[0];
        acc += w3 * p3[0];
    }
    for (; i < cnt; i++) acc += sw[i] * xr[(size_t)ssrc[i] * DD];

    g_H[((size_t)n * RR + r) * DD + t] = acc;
}

// ---------------------------------------------------------------------------
// One block per node n. Thread t owns column d=t for all R relations.
// Keeps all K*R diffs in registers; candidate rows read exactly once.
__global__ __launch_bounds__(256) void mask_kernel(
    const int* __restrict__ cand,   // [N, K]
    float*     __restrict__ out)    // [N, D]
{
    const int n = blockIdx.x;
    const int t = threadIdx.x;
    const int lane = t & 31, w = t >> 5;

    __shared__ float wsum[8 * KK];
    __shared__ float sdist[KK];

    float own[RR];
    #pragma unroll
    for (int r = 0; r < RR; r++)
        own[r] = g_H[((size_t)n * RR + r) * DD + t];

    float diff[KK][RR];
    float p[KK];
    #pragma unroll
    for (int k = 0; k < KK; k++) {
        int c = cand[n * KK + k];
        const float* cr = &g_H[(size_t)c * RR * DD + t];
        float s = 0.f;
        #pragma unroll
        for (int r = 0; r < RR; r++) {
            float dv = own[r] - cr[(size_t)r * DD];
            diff[k][r] = dv;
            s += dv * dv;
        }
        p[k] = s;
    }

    // 16 block reductions (warp shuffle + cross-warp)
    #pragma unroll
    for (int k = 0; k < KK; k++) {
        float v = p[k];
        #pragma unroll
        for (int o = 16; o; o >>= 1) v += __shfl_xor_sync(0xffffffffu, v, o);
        if (lane == 0) wsum[w * KK + k] = v;
    }
    __syncthreads();
    if (t < KK) {
        float s = 0.f;
        #pragma unroll
        for (int ww = 0; ww < 8; ww++) s += wsum[ww * KK + t];
        sdist[t] = sqrtf(s);
    }
    __syncthreads();

    // softmax over -dist (redundant per thread; cheap, avoids extra syncs)
    float mn = sdist[0];
    #pragma unroll
    for (int k = 1; k < KK; k++) mn = fminf(mn, sdist[k]);
    float att[KK];
    float asum = 0.f;
    #pragma unroll
    for (int k = 0; k < KK; k++) {
        float e = expf(mn - sdist[k]);
        att[k] = e;
        asum += e;
    }
    const float inv = 1.f / asum;

    float o = 0.f;
    #pragma unroll
    for (int r = 0; r < RR; r++) {
        float s = 0.f;
        #pragma unroll
        for (int k = 0; k < KK; k++) s += att[k] * diff[k][r] * diff[k][r];
        o += own[r] * expf(-s * inv);
    }
    out[(size_t)n * DD + t] = o;
}

// ---------------------------------------------------------------------------
extern "C" void kernel_launch(void* const* d_in, const int* in_sizes, int n_in,
                              void* d_out, int out_size)
{
    const float* x    = (const float*)d_in[0];   // [R, NSRC, D]
    const float* d    = (const float*)d_in[1];   // [R, NSRC]
    const float* d1   = (const float*)d_in[2];
    const float* d2   = (const float*)d_in[3];
    const int*   src  = (const int*)d_in[4];     // [R, E]
    const int*   dst  = (const int*)d_in[5];     // [R, E]
    const int*   cand = (const int*)d_in[6];     // [N, K]
    const int*   split = (n_in >= 8) ? (const int*)d_in[7] : nullptr;
    float* out = (float*)d_out;

    (void)in_sizes; (void)out_size;

    zero_cnt_kernel<<<(RR * NN + 255) / 256, 256>>>();
    bucket_kernel<<<(RR * EE + 255) / 256, 256>>>(src, dst);
    agg_kernel<<<RR * NN, 256>>>(x, d, d1, d2, split);
    mask_kernel<<<NN, 256>>>(cand, out);
}

// round 2
// speedup vs baseline: 1.3305x; 1.3305x over previous
#include <cuda_runtime.h>
#include <cuda_fp16.h>
#include <math.h>

// Problem constants (fixed instance)
#define RR   4
#define NN   20000
#define NSRC 20000
#define DD   256
#define EE   640000
#define KK   16
#define CAP  128       // max edges per (relation, dst); Poisson(32) tail -> safe

// Static scratch (allocation-free rule)
__device__ int   g_cnt[RR * NN];
__device__ int   g_slots[(size_t)RR * NN * CAP];
__device__ float g_H[(size_t)NN * RR * DD];        // [N][R][D] -> node row = 1024 contiguous floats

// ---------------------------------------------------------------------------
__global__ void zero_cnt_kernel() {
    int i = blockIdx.x * blockDim.x + threadIdx.x;
    if (i < RR * NN) g_cnt[i] = 0;
}

__global__ void bucket_kernel(const int* __restrict__ src_idx,
                              const int* __restrict__ dst_idx) {
    int idx = blockIdx.x * blockDim.x + threadIdx.x;
    if (idx >= RR * EE) return;
    int r   = idx / EE;
    int dst = dst_idx[idx];
    int src = src_idx[idx];
    int b   = r * NN + dst;
    int rank = atomicAdd(&g_cnt[b], 1);
    if (rank < CAP) g_slots[(size_t)b * CAP + rank] = src;
}

// ---------------------------------------------------------------------------
// One block per node n; four 64-thread groups, group g handles relation r=g.
// Each group: segment softmax (selected branch) + float4 weighted gather-sum.
__global__ __launch_bounds__(256) void agg_kernel(
    const float* __restrict__ x,    // [R, NSRC, D]
    const float* __restrict__ d,    // [R, NSRC]
    const float* __restrict__ d1,
    const float* __restrict__ d2,
    const int*   __restrict__ split_p)
{
    const int n  = blockIdx.x;
    const int t  = threadIdx.x;
    const int g  = t >> 6;         // relation / group id
    const int tg = t & 63;         // lane within group
    const int wg = (t >> 5) & 1;   // warp within group

    __shared__ int   ssrc[RR][CAP];
    __shared__ float sw[RR][CAP];
    __shared__ float red[RR][2];

    int cnt = g_cnt[g * NN + n];
    if (cnt > CAP) cnt = CAP;

    const int split = split_p ? __ldg(split_p) : 10000;
    const bool use1 = (n < split);

    // logits
    for (int i = tg; i < cnt; i += 64) {
        int s = g_slots[((size_t)g * NN + n) * CAP + i];
        ssrc[g][i] = s;
        float dv = d[g * NSRC + s];
        sw[g][i] = use1 ? (d1[g * NSRC + s] / dv)
                        : (-d2[g * NSRC + s] / dv);
    }
    __syncthreads();

    // max over up to 128 logits: 2 slots per thread
    float v = -1e30f;
    if (tg       < cnt) v = sw[g][tg];
    if (tg + 64  < cnt) v = fmaxf(v, sw[g][tg + 64]);
    #pragma unroll
    for (int o = 16; o; o >>= 1) v = fmaxf(v, __shfl_xor_sync(0xffffffffu, v, o));
    if ((t & 31) == 0) red[g][wg] = v;
    __syncthreads();
    const float m = fmaxf(red[g][0], red[g][1]);
    __syncthreads();   // red about to be overwritten

    float e0 = 0.f, e1 = 0.f;
    if (tg      < cnt) { e0 = __expf(sw[g][tg]      - m); sw[g][tg]      = e0; }
    if (tg + 64 < cnt) { e1 = __expf(sw[g][tg + 64] - m); sw[g][tg + 64] = e1; }
    float sv = e0 + e1;
    #pragma unroll
    for (int o = 16; o; o >>= 1) sv += __shfl_xor_sync(0xffffffffu, sv, o);
    if ((t & 31) == 0) red[g][wg] = sv;
    __syncthreads();
    const float winv = 1.f / fmaxf(red[g][0] + red[g][1], 1e-9f);
    if (tg      < cnt) sw[g][tg]      *= winv;
    if (tg + 64 < cnt) sw[g][tg + 64] *= winv;
    __syncthreads();

    // float4 weighted gather-sum: thread tg owns 16B chunk tg of each 1KB row
    const float4* xr = (const float4*)(x + (size_t)g * NSRC * DD) + tg;
    float4 acc = make_float4(0.f, 0.f, 0.f, 0.f);
    int i = 0;
    for (; i + 4 <= cnt; i += 4) {
        float w0 = sw[g][i], w1 = sw[g][i+1], w2 = sw[g][i+2], w3 = sw[g][i+3];
        float4 v0 = xr[(size_t)ssrc[g][i]   * 64];
        float4 v1 = xr[(size_t)ssrc[g][i+1] * 64];
        float4 v2 = xr[(size_t)ssrc[g][i+2] * 64];
        float4 v3 = xr[(size_t)ssrc[g][i+3] * 64];
        acc.x += w0*v0.x + w1*v1.x + w2*v2.x + w3*v3.x;
        acc.y += w0*v0.y + w1*v1.y + w2*v2.y + w3*v3.y;
        acc.z += w0*v0.z + w1*v1.z + w2*v2.z + w3*v3.z;
        acc.w += w0*v0.w + w1*v1.w + w2*v2.w + w3*v3.w;
    }
    for (; i < cnt; i++) {
        float w0 = sw[g][i];
        float4 v0 = xr[(size_t)ssrc[g][i] * 64];
        acc.x += w0*v0.x; acc.y += w0*v0.y; acc.z += w0*v0.z; acc.w += w0*v0.w;
    }
    ((float4*)(g_H + ((size_t)n * RR + g) * DD))[tg] = acc;
}

// ---------------------------------------------------------------------------
// One block per node. Flattened [R*D]=1024 elements; thread t owns float4 at 4t.
// Diffs for all K candidates stored as fp16 in smem (32KB) to keep regs low.
__global__ __launch_bounds__(256) void mask_kernel(
    const int* __restrict__ cand,   // [N, K]
    float*     __restrict__ out)    // [N, D]
{
    const int n = blockIdx.x;
    const int t = threadIdx.x;
    const int lane = t & 31, w = t >> 5;

    __shared__ __half2 sdiff[KK][512];   // 16 x 1024 halves = 32KB
    __shared__ float   wsum[8 * KK];
    __shared__ float   satt[KK];
    __shared__ float   sval[RR * DD];    // 4KB staging for cross-relation sum

    const float4 own = ((const float4*)(g_H + (size_t)n * (RR * DD)))[t];

    float p[KK];
    #pragma unroll
    for (int k = 0; k < KK; k++) {
        int c = cand[n * KK + k];
        float4 cv = ((const float4*)(g_H + (size_t)c * (RR * DD)))[t];
        float dx = own.x - cv.x, dy = own.y - cv.y;
        float dz = own.z - cv.z, dw = own.w - cv.w;
        sdiff[k][2*t]   = __floats2half2_rn(dx, dy);
        sdiff[k][2*t+1] = __floats2half2_rn(dz, dw);
        p[k] = dx*dx + dy*dy + dz*dz + dw*dw;
    }

    #pragma unroll
    for (int k = 0; k < KK; k++) {
        float v = p[k];
        #pragma unroll
        for (int o = 16; o; o >>= 1) v += __shfl_xor_sync(0xffffffffu, v, o);
        if (lane == 0) wsum[w * KK + k] = v;
    }
    __syncthreads();

    // warp 0 finishes: dist -> softmax(-dist) -> normalized att in smem
    if (t < 32) {
        float dist = 1e30f;
        if (t < KK) {
            float s = 0.f;
            #pragma unroll
            for (int ww = 0; ww < 8; ww++) s += wsum[ww * KK + t];
            dist = sqrtf(s);
        }
        float mn = dist;
        #pragma unroll
        for (int o = 16; o; o >>= 1) mn = fminf(mn, __shfl_xor_sync(0xffffffffu, mn, o));
        float e = (t < KK) ? __expf(mn - dist) : 0.f;
        float s = e;
        #pragma unroll
        for (int o = 16; o; o >>= 1) s += __shfl_xor_sync(0xffffffffu, s, o);
        if (t < KK) satt[t] = e / s;
    }
    __syncthreads();

    // s[e] = sum_k att_k * diff_k[e]^2 ; val = own * exp(-s)
    float sx = 0.f, sy = 0.f, sz = 0.f, sw_ = 0.f;
    #pragma unroll
    for (int k = 0; k < KK; k++) {
        float a = satt[k];
        float2 d01 = __half22float2(sdiff[k][2*t]);
        float2 d23 = __half22float2(sdiff[k][2*t+1]);
        sx += a * d01.x * d01.x;
        sy += a * d01.y * d01.y;
        sz += a * d23.x * d23.x;
        sw_ += a * d23.y * d23.y;
    }
    float4 val;
    val.x = own.x * __expf(-sx);
    val.y = own.y * __expf(-sy);
    val.z = own.z * __expf(-sz);
    val.w = own.w * __expf(-sw_);
    ((float4*)sval)[t] = val;
    __syncthreads();

    // out[n][d] = sum_r val[r][d] ; threads 0..63 each own a float4 of d
    if (t < 64) {
        float4 a0 = ((float4*)sval)[t];
        float4 a1 = ((float4*)sval)[t + 64];
        float4 a2 = ((float4*)sval)[t + 128];
        float4 a3 = ((float4*)sval)[t + 192];
        float4 o;
        o.x = a0.x + a1.x + a2.x + a3.x;
        o.y = a0.y + a1.y + a2.y + a3.y;
        o.z = a0.z + a1.z + a2.z + a3.z;
        o.w = a0.w + a1.w + a2.w + a3.w;
        ((float4*)(out + (size_t)n * DD))[t] = o;
    }
}

// ---------------------------------------------------------------------------
extern "C" void kernel_launch(void* const* d_in, const int* in_sizes, int n_in,
                              void* d_out, int out_size)
{
    const float* x    = (const float*)d_in[0];
    const float* d    = (const float*)d_in[1];
    const float* d1   = (const float*)d_in[2];
    const float* d2   = (const float*)d_in[3];
    const int*   src  = (const int*)d_in[4];
    const int*   dst  = (const int*)d_in[5];
    const int*   cand = (const int*)d_in[6];
    const int*   split = (n_in >= 8) ? (const int*)d_in[7] : nullptr;
    float* out = (float*)d_out;

    (void)in_sizes; (void)out_size;

    zero_cnt_kernel<<<(RR * NN + 255) / 256, 256>>>();
    bucket_kernel<<<(RR * EE + 255) / 256, 256>>>(src, dst);
    agg_kernel<<<NN, 256>>>(x, d, d1, d2, split);
    mask_kernel<<<NN, 256>>>(cand, out);
}

// round 3
// speedup vs baseline: 1.7044x; 1.2811x over previous
#include <cuda_runtime.h>
#include <cuda_fp16.h>
#include <math.h>

// Problem constants (fixed instance)
#define RR   4
#define NN   20000
#define NSRC 20000
#define DD   256
#define EE   640000
#define KK   16
#define CAP  128       // max edges per (relation, dst); Poisson(32) tail -> safe

// Static scratch (allocation-free rule)
__device__ int    g_cnt[RR * NN];
__device__ int    g_slots[(size_t)RR * NN * CAP];
__device__ __half g_H16[(size_t)NN * RR * DD];      // [N][R*D] fp16 (40MB, L2-resident)
__device__ __half g_x16[(size_t)RR * NSRC * DD];    // fp16 copy of x (40MB)

// ---------------------------------------------------------------------------
__global__ void zero_cnt_kernel() {
    int i = blockIdx.x * blockDim.x + threadIdx.x;
    if (i < RR * NN) g_cnt[i] = 0;
}

// x (fp32) -> g_x16 (fp16), float4 -> 2x half2 per thread
__global__ void convert_x_kernel(const float* __restrict__ x) {
    size_t i = (size_t)blockIdx.x * blockDim.x + threadIdx.x;   // float4 index
    const size_t total = (size_t)RR * NSRC * DD / 4;
    if (i >= total) return;
    float4 v = ((const float4*)x)[i];
    __half2 h0 = __floats2half2_rn(v.x, v.y);
    __half2 h1 = __floats2half2_rn(v.z, v.w);
    uint2 packed;
    packed.x = *(const unsigned*)&h0;
    packed.y = *(const unsigned*)&h1;
    ((uint2*)g_x16)[i] = packed;
}

__global__ void bucket_kernel(const int* __restrict__ src_idx,
                              const int* __restrict__ dst_idx) {
    int idx = blockIdx.x * blockDim.x + threadIdx.x;
    if (idx >= RR * EE) return;
    int r   = idx / EE;
    int dst = dst_idx[idx];
    int src = src_idx[idx];
    int b   = r * NN + dst;
    int rank = atomicAdd(&g_cnt[b], 1);
    if (rank < CAP) g_slots[(size_t)b * CAP + rank] = src;
}

// ---------------------------------------------------------------------------
// One block per node n; four 64-thread groups, group g handles relation r=g.
// Segment softmax (selected branch) + fp16 weighted gather-sum (fp32 accum).
__global__ __launch_bounds__(256) void agg_kernel(
    const float* __restrict__ d,    // [R, NSRC]
    const float* __restrict__ d1,
    const float* __restrict__ d2,
    const int*   __restrict__ split_p)
{
    const int n  = blockIdx.x;
    const int t  = threadIdx.x;
    const int g  = t >> 6;         // relation
    const int tg = t & 63;
    const int wg = (t >> 5) & 1;

    __shared__ int   ssrc[RR][CAP];
    __shared__ float sw[RR][CAP];
    __shared__ float red[RR][2];

    int cnt = g_cnt[g * NN + n];
    if (cnt > CAP) cnt = CAP;

    const int split = split_p ? __ldg(split_p) : 10000;
    const bool use1 = (n < split);

    for (int i = tg; i < cnt; i += 64) {
        int s = g_slots[((size_t)g * NN + n) * CAP + i];
        ssrc[g][i] = s;
        float dv = d[g * NSRC + s];
        sw[g][i] = use1 ? (d1[g * NSRC + s] / dv)
                        : (-d2[g * NSRC + s] / dv);
    }
    __syncthreads();

    float v = -1e30f;
    if (tg       < cnt) v = sw[g][tg];
    if (tg + 64  < cnt) v = fmaxf(v, sw[g][tg + 64]);
    #pragma unroll
    for (int o = 16; o; o >>= 1) v = fmaxf(v, __shfl_xor_sync(0xffffffffu, v, o));
    if ((t & 31) == 0) red[g][wg] = v;
    __syncthreads();
    const float m = fmaxf(red[g][0], red[g][1]);
    __syncthreads();

    float e0 = 0.f, e1 = 0.f;
    if (tg      < cnt) { e0 = __expf(sw[g][tg]      - m); sw[g][tg]      = e0; }
    if (tg + 64 < cnt) { e1 = __expf(sw[g][tg + 64] - m); sw[g][tg + 64] = e1; }
    float sv = e0 + e1;
    #pragma unroll
    for (int o = 16; o; o >>= 1) sv += __shfl_xor_sync(0xffffffffu, sv, o);
    if ((t & 31) == 0) red[g][wg] = sv;
    __syncthreads();
    const float winv = 1.f / fmaxf(red[g][0] + red[g][1], 1e-9f);
    if (tg      < cnt) sw[g][tg]      *= winv;
    if (tg + 64 < cnt) sw[g][tg + 64] *= winv;
    __syncthreads();

    // fp16 gather: thread tg owns 4 elements (one uint2 = 2 half2) of the 512B row
    const uint2* xr = (const uint2*)(g_x16 + (size_t)g * NSRC * DD) + tg;  // row stride 64 uint2
    float ax = 0.f, ay = 0.f, az = 0.f, aw = 0.f;
    int i = 0;
    for (; i + 4 <= cnt; i += 4) {
        float w0 = sw[g][i], w1 = sw[g][i+1], w2 = sw[g][i+2], w3 = sw[g][i+3];
        uint2 u0 = xr[(size_t)ssrc[g][i]   * 64];
        uint2 u1 = xr[(size_t)ssrc[g][i+1] * 64];
        uint2 u2 = xr[(size_t)ssrc[g][i+2] * 64];
        uint2 u3 = xr[(size_t)ssrc[g][i+3] * 64];
        float2 a0 = __half22float2(*(__half2*)&u0.x), b0 = __half22float2(*(__half2*)&u0.y);
        float2 a1 = __half22float2(*(__half2*)&u1.x), b1 = __half22float2(*(__half2*)&u1.y);
        float2 a2 = __half22float2(*(__half2*)&u2.x), b2 = __half22float2(*(__half2*)&u2.y);
        float2 a3 = __half22float2(*(__half2*)&u3.x), b3 = __half22float2(*(__half2*)&u3.y);
        ax += w0*a0.x + w1*a1.x + w2*a2.x + w3*a3.x;
        ay += w0*a0.y + w1*a1.y + w2*a2.y + w3*a3.y;
        az += w0*b0.x + w1*b1.x + w2*b2.x + w3*b3.x;
        aw += w0*b0.y + w1*b1.y + w2*b2.y + w3*b3.y;
    }
    for (; i < cnt; i++) {
        float w0 = sw[g][i];
        uint2 u0 = xr[(size_t)ssrc[g][i] * 64];
        float2 a0 = __half22float2(*(__half2*)&u0.x), b0 = __half22float2(*(__half2*)&u0.y);
        ax += w0*a0.x; ay += w0*a0.y; az += w0*b0.x; aw += w0*b0.y;
    }
    __half2 h0 = __floats2half2_rn(ax, ay);
    __half2 h1 = __floats2half2_rn(az, aw);
    uint2 packed;
    packed.x = *(const unsigned*)&h0;
    packed.y = *(const unsigned*)&h1;
    ((uint2*)(g_H16 + ((size_t)n * RR + g) * DD))[tg] = packed;
}

// ---------------------------------------------------------------------------
// One block per node. Flattened [R*D]=1024 elements; thread t owns 4 (one uint2).
// All K diffs held in registers as half2; no smem diff array.
__global__ __launch_bounds__(256) void mask_kernel(
    const int* __restrict__ cand,   // [N, K]
    float*     __restrict__ out)    // [N, D]
{
    const int n = blockIdx.x;
    const int t = threadIdx.x;
    const int lane = t & 31, w = t >> 5;

    __shared__ int   scand[KK];
    __shared__ float wsum[8 * KK];
    __shared__ float satt[KK];
    __shared__ float sval[RR * DD];   // 4KB staging

    if (t < KK) scand[t] = cand[n * KK + t];
    __syncthreads();

    const uint2 ownu = ((const uint2*)(g_H16 + (size_t)n * (RR * DD)))[t];
    const __half2 own0 = *(const __half2*)&ownu.x;
    const __half2 own1 = *(const __half2*)&ownu.y;

    __half2 diff0[KK], diff1[KK];
    float p[KK];
    #pragma unroll
    for (int k = 0; k < KK; k++) {
        uint2 cu = ((const uint2*)(g_H16 + (size_t)scand[k] * (RR * DD)))[t];
        __half2 d0 = __hsub2(own0, *(const __half2*)&cu.x);
        __half2 d1 = __hsub2(own1, *(const __half2*)&cu.y);
        diff0[k] = d0; diff1[k] = d1;
        float2 f0 = __half22float2(d0), f1 = __half22float2(d1);
        p[k] = f0.x*f0.x + f0.y*f0.y + f1.x*f1.x + f1.y*f1.y;
    }

    #pragma unroll
    for (int k = 0; k < KK; k++) {
        float v = p[k];
        #pragma unroll
        for (int o = 16; o; o >>= 1) v += __shfl_xor_sync(0xffffffffu, v, o);
        if (lane == 0) wsum[w * KK + k] = v;
    }
    __syncthreads();

    if (t < 32) {
        float dist = 1e30f;
        if (t < KK) {
            float s = 0.f;
            #pragma unroll
            for (int ww = 0; ww < 8; ww++) s += wsum[ww * KK + t];
            dist = sqrtf(s);
        }
        float mn = dist;
        #pragma unroll
        for (int o = 16; o; o >>= 1) mn = fminf(mn, __shfl_xor_sync(0xffffffffu, mn, o));
        float e = (t < KK) ? __expf(mn - dist) : 0.f;
        float s = e;
        #pragma unroll
        for (int o = 16; o; o >>= 1) s += __shfl_xor_sync(0xffffffffu, s, o);
        if (t < KK) satt[t] = e / s;
    }
    __syncthreads();

    float sx = 0.f, sy = 0.f, sz = 0.f, sw_ = 0.f;
    #pragma unroll
    for (int k = 0; k < KK; k++) {
        float a = satt[k];
        float2 f0 = __half22float2(diff0[k]);
        float2 f1 = __half22float2(diff1[k]);
        sx  += a * f0.x * f0.x;
        sy  += a * f0.y * f0.y;
        sz  += a * f1.x * f1.x;
        sw_ += a * f1.y * f1.y;
    }
    float2 o0 = __half22float2(own0);
    float2 o1 = __half22float2(own1);
    float4 val;
    val.x = o0.x * __expf(-sx);
    val.y = o0.y * __expf(-sy);
    val.z = o1.x * __expf(-sz);
    val.w = o1.y * __expf(-sw_);
    ((float4*)sval)[t] = val;
    __syncthreads();

    if (t < 64) {
        float4 a0 = ((float4*)sval)[t];
        float4 a1 = ((float4*)sval)[t + 64];
        float4 a2 = ((float4*)sval)[t + 128];
        float4 a3 = ((float4*)sval)[t + 192];
        float4 o;
        o.x = a0.x + a1.x + a2.x + a3.x;
        o.y = a0.y + a1.y + a2.y + a3.y;
        o.z = a0.z + a1.z + a2.z + a3.z;
        o.w = a0.w + a1.w + a2.w + a3.w;
        ((float4*)(out + (size_t)n * DD))[t] = o;
    }
}

// ---------------------------------------------------------------------------
extern "C" void kernel_launch(void* const* d_in, const int* in_sizes, int n_in,
                              void* d_out, int out_size)
{
    const float* x    = (const float*)d_in[0];
    const float* d    = (const float*)d_in[1];
    const float* d1   = (const float*)d_in[2];
    const float* d2   = (const float*)d_in[3];
    const int*   src  = (const int*)d_in[4];
    const int*   dst  = (const int*)d_in[5];
    const int*   cand = (const int*)d_in[6];
    const int*   split = (n_in >= 8) ? (const int*)d_in[7] : nullptr;
    float* out = (float*)d_out;

    (void)in_sizes; (void)out_size;

    zero_cnt_kernel<<<(RR * NN + 255) / 256, 256>>>();
    convert_x_kernel<<<((RR * NSRC * DD / 4) + 255) / 256, 256>>>(x);
    bucket_kernel<<<(RR * EE + 255) / 256, 256>>>(src, dst);
    agg_kernel<<<NN, 256>>>(d, d1, d2, split);
    mask_kernel<<<NN, 256>>>(cand, out);
}

// round 4
// speedup vs baseline: 1.8912x; 1.1096x over previous
#include <cuda_runtime.h>
#include <cuda_fp16.h>
#include <math.h>

// Problem constants (fixed instance)
#define RR   4
#define NN   20000
#define NSRC 20000
#define DD   256
#define EE   640000
#define KK   16
#define CAP  96        // max edges per (relation, dst); Poisson(32), max ~60 observed regime

// Static scratch (allocation-free rule)
__device__ int            g_cnt[RR * NN];
__device__ unsigned short g_slots16[(size_t)RR * NN * CAP];   // src ids fit in u16
__device__ __half         g_H16[(size_t)NN * RR * DD];        // [N][R*D] fp16 (40MB)
__device__ __half         g_x16[(size_t)RR * NSRC * DD];      // fp16 x (40MB)

// ---------------------------------------------------------------------------
__global__ void zero_cnt_kernel() {
    int i = blockIdx.x * blockDim.x + threadIdx.x;
    if (i < RR * NN) g_cnt[i] = 0;
}

// x (fp32) -> g_x16 (fp16); 8 floats per thread, 16B stores
__global__ void convert_x_kernel(const float* __restrict__ x) {
    size_t i = (size_t)blockIdx.x * blockDim.x + threadIdx.x;   // group of 8 floats
    const size_t total = (size_t)RR * NSRC * DD / 8;
    if (i >= total) return;
    float4 v0 = ((const float4*)x)[2 * i];
    float4 v1 = ((const float4*)x)[2 * i + 1];
    __half2 h0 = __floats2half2_rn(v0.x, v0.y);
    __half2 h1 = __floats2half2_rn(v0.z, v0.w);
    __half2 h2 = __floats2half2_rn(v1.x, v1.y);
    __half2 h3 = __floats2half2_rn(v1.z, v1.w);
    uint4 packed;
    packed.x = *(const unsigned*)&h0;
    packed.y = *(const unsigned*)&h1;
    packed.z = *(const unsigned*)&h2;
    packed.w = *(const unsigned*)&h3;
    ((uint4*)g_x16)[i] = packed;
}

__global__ void bucket_kernel(const int* __restrict__ src_idx,
                              const int* __restrict__ dst_idx) {
    int e = blockIdx.x * blockDim.x + threadIdx.x;
    int r = blockIdx.y;
    if (e >= EE) return;
    int dst = dst_idx[(size_t)r * EE + e];
    int src = src_idx[(size_t)r * EE + e];
    int b   = r * NN + dst;
    int rank = atomicAdd(&g_cnt[b], 1);
    if (rank < CAP) g_slots16[(size_t)b * CAP + rank] = (unsigned short)src;
}

// ---------------------------------------------------------------------------
// One WARP per (n, r) pair. Warp-local softmax (no block syncs), then uint4
// fp16 gather: lane owns 16B chunk `lane` of the 512B row.
__global__ __launch_bounds__(256) void agg_kernel(
    const float* __restrict__ d,    // [R, NSRC]
    const float* __restrict__ d1,
    const float* __restrict__ d2,
    const int*   __restrict__ split_p)
{
    const int warp = threadIdx.x >> 5;
    const int lane = threadIdx.x & 31;
    const int p = blockIdx.x * 8 + warp;      // 0 .. 80000
    const int n = p >> 2;
    const int g = p & 3;

    __shared__ float          sw[8][CAP];
    __shared__ unsigned short ssrc[8][CAP];

    int cnt = g_cnt[g * NN + n];
    if (cnt > CAP) cnt = CAP;

    const int split = split_p ? __ldg(split_p) : 10000;
    const bool use1 = (n < split);

    const unsigned short* slot = g_slots16 + ((size_t)g * NN + n) * CAP;

    // logits: up to 3 per lane (CAP=96)
    float l[3];
    int   s[3];
    #pragma unroll
    for (int j = 0; j < 3; j++) {
        int i = lane + 32 * j;
        l[j] = -1e30f; s[j] = 0;
        if (i < cnt) {
            int sv = slot[i];
            s[j] = sv;
            float dv = d[g * NSRC + sv];
            l[j] = use1 ? (d1[g * NSRC + sv] / dv)
                        : (-d2[g * NSRC + sv] / dv);
        }
    }
    float m = fmaxf(fmaxf(l[0], l[1]), l[2]);
    #pragma unroll
    for (int o = 16; o; o >>= 1) m = fmaxf(m, __shfl_xor_sync(0xffffffffu, m, o));

    float e[3];
    float sum = 0.f;
    #pragma unroll
    for (int j = 0; j < 3; j++) {
        e[j] = (lane + 32 * j < cnt) ? __expf(l[j] - m) : 0.f;
        sum += e[j];
    }
    #pragma unroll
    for (int o = 16; o; o >>= 1) sum += __shfl_xor_sync(0xffffffffu, sum, o);
    const float winv = 1.f / fmaxf(sum, 1e-9f);

    #pragma unroll
    for (int j = 0; j < 3; j++) {
        int i = lane + 32 * j;
        if (i < cnt) { sw[warp][i] = e[j] * winv; ssrc[warp][i] = (unsigned short)s[j]; }
    }
    __syncwarp();

    // gather: row = 32 uint4; lane owns chunk `lane`
    const uint4* xr = (const uint4*)g_x16 + (size_t)g * NSRC * 32 + lane;
    float a0=0,a1=0,a2=0,a3=0,a4=0,a5=0,a6=0,a7=0;

    int i = 0;
    for (; i + 4 <= cnt; i += 4) {
        float w0 = sw[warp][i],   w1 = sw[warp][i+1];
        float w2 = sw[warp][i+2], w3 = sw[warp][i+3];
        uint4 u0 = xr[(size_t)ssrc[warp][i]   * 32];
        uint4 u1 = xr[(size_t)ssrc[warp][i+1] * 32];
        uint4 u2 = xr[(size_t)ssrc[warp][i+2] * 32];
        uint4 u3 = xr[(size_t)ssrc[warp][i+3] * 32];
        {
            float2 f0=__half22float2(*(__half2*)&u0.x), f1=__half22float2(*(__half2*)&u0.y);
            float2 f2=__half22float2(*(__half2*)&u0.z), f3=__half22float2(*(__half2*)&u0.w);
            a0+=w0*f0.x; a1+=w0*f0.y; a2+=w0*f1.x; a3+=w0*f1.y;
            a4+=w0*f2.x; a5+=w0*f2.y; a6+=w0*f3.x; a7+=w0*f3.y;
        }
        {
            float2 f0=__half22float2(*(__half2*)&u1.x), f1=__half22float2(*(__half2*)&u1.y);
            float2 f2=__half22float2(*(__half2*)&u1.z), f3=__half22float2(*(__half2*)&u1.w);
            a0+=w1*f0.x; a1+=w1*f0.y; a2+=w1*f1.x; a3+=w1*f1.y;
            a4+=w1*f2.x; a5+=w1*f2.y; a6+=w1*f3.x; a7+=w1*f3.y;
        }
        {
            float2 f0=__half22float2(*(__half2*)&u2.x), f1=__half22float2(*(__half2*)&u2.y);
            float2 f2=__half22float2(*(__half2*)&u2.z), f3=__half22float2(*(__half2*)&u2.w);
            a0+=w2*f0.x; a1+=w2*f0.y; a2+=w2*f1.x; a3+=w2*f1.y;
            a4+=w2*f2.x; a5+=w2*f2.y; a6+=w2*f3.x; a7+=w2*f3.y;
        }
        {
            float2 f0=__half22float2(*(__half2*)&u3.x), f1=__half22float2(*(__half2*)&u3.y);
            float2 f2=__half22float2(*(__half2*)&u3.z), f3=__half22float2(*(__half2*)&u3.w);
            a0+=w3*f0.x; a1+=w3*f0.y; a2+=w3*f1.x; a3+=w3*f1.y;
            a4+=w3*f2.x; a5+=w3*f2.y; a6+=w3*f3.x; a7+=w3*f3.y;
        }
    }
    for (; i < cnt; i++) {
        float w0 = sw[warp][i];
        uint4 u0 = xr[(size_t)ssrc[warp][i] * 32];
        float2 f0=__half22float2(*(__half2*)&u0.x), f1=__half22float2(*(__half2*)&u0.y);
        float2 f2=__half22float2(*(__half2*)&u0.z), f3=__half22float2(*(__half2*)&u0.w);
        a0+=w0*f0.x; a1+=w0*f0.y; a2+=w0*f1.x; a3+=w0*f1.y;
        a4+=w0*f2.x; a5+=w0*f2.y; a6+=w0*f3.x; a7+=w0*f3.y;
    }

    __half2 h0 = __floats2half2_rn(a0, a1);
    __half2 h1 = __floats2half2_rn(a2, a3);
    __half2 h2 = __floats2half2_rn(a4, a5);
    __half2 h3 = __floats2half2_rn(a6, a7);
    uint4 packed;
    packed.x = *(const unsigned*)&h0;
    packed.y = *(const unsigned*)&h1;
    packed.z = *(const unsigned*)&h2;
    packed.w = *(const unsigned*)&h3;
    ((uint4*)(g_H16 + ((size_t)n * RR + g) * DD))[lane] = packed;
}

// ---------------------------------------------------------------------------
// One block per node. Flattened [R*D]=1024 elems; thread t owns 4 (one uint2).
// All K diffs in registers as half2.
__global__ __launch_bounds__(256) void mask_kernel(
    const int* __restrict__ cand,   // [N, K]
    float*     __restrict__ out)    // [N, D]
{
    const int n = blockIdx.x;
    const int t = threadIdx.x;
    const int lane = t & 31, w = t >> 5;

    __shared__ int   scand[KK];
    __shared__ float wsum[8 * KK];
    __shared__ float satt[KK];
    __shared__ float sval[RR * DD];

    if (t < KK) scand[t] = cand[n * KK + t];
    __syncthreads();

    const uint2 ownu = ((const uint2*)(g_H16 + (size_t)n * (RR * DD)))[t];
    const __half2 own0 = *(const __half2*)&ownu.x;
    const __half2 own1 = *(const __half2*)&ownu.y;

    __half2 diff0[KK], diff1[KK];
    float p[KK];
    #pragma unroll
    for (int k = 0; k < KK; k++) {
        uint2 cu = ((const uint2*)(g_H16 + (size_t)scand[k] * (RR * DD)))[t];
        __half2 d0 = __hsub2(own0, *(const __half2*)&cu.x);
        __half2 d1 = __hsub2(own1, *(const __half2*)&cu.y);
        diff0[k] = d0; diff1[k] = d1;
        float2 f0 = __half22float2(d0), f1 = __half22float2(d1);
        p[k] = f0.x*f0.x + f0.y*f0.y + f1.x*f1.x + f1.y*f1.y;
    }

    #pragma unroll
    for (int k = 0; k < KK; k++) {
        float v = p[k];
        #pragma unroll
        for (int o = 16; o; o >>= 1) v += __shfl_xor_sync(0xffffffffu, v, o);
        if (lane == 0) wsum[w * KK + k] = v;
    }
    __syncthreads();

    if (t < 32) {
        float dist = 1e30f;
        if (t < KK) {
            float s = 0.f;
            #pragma unroll
            for (int ww = 0; ww < 8; ww++) s += wsum[ww * KK + t];
            dist = sqrtf(s);
        }
        float mn = dist;
        #pragma unroll
        for (int o = 16; o; o >>= 1) mn = fminf(mn, __shfl_xor_sync(0xffffffffu, mn, o));
        float e = (t < KK) ? __expf(mn - dist) : 0.f;
        float s = e;
        #pragma unroll
        for (int o = 16; o; o >>= 1) s += __shfl_xor_sync(0xffffffffu, s, o);
        if (t < KK) satt[t] = e / s;
    }
    __syncthreads();

    float sx = 0.f, sy = 0.f, sz = 0.f, sw_ = 0.f;
    #pragma unroll
    for (int k = 0; k < KK; k++) {
        float a = satt[k];
        float2 f0 = __half22float2(diff0[k]);
        float2 f1 = __half22float2(diff1[k]);
        sx  += a * f0.x * f0.x;
        sy  += a * f0.y * f0.y;
        sz  += a * f1.x * f1.x;
        sw_ += a * f1.y * f1.y;
    }
    float2 o0 = __half22float2(own0);
    float2 o1 = __half22float2(own1);
    float4 val;
    val.x = o0.x * __expf(-sx);
    val.y = o0.y * __expf(-sy);
    val.z = o1.x * __expf(-sz);
    val.w = o1.y * __expf(-sw_);
    ((float4*)sval)[t] = val;
    __syncthreads();

    if (t < 64) {
        float4 b0 = ((float4*)sval)[t];
        float4 b1 = ((float4*)sval)[t + 64];
        float4 b2 = ((float4*)sval)[t + 128];
        float4 b3 = ((float4*)sval)[t + 192];
        float4 o;
        o.x = b0.x + b1.x + b2.x + b3.x;
        o.y = b0.y + b1.y + b2.y + b3.y;
        o.z = b0.z + b1.z + b2.z + b3.z;
        o.w = b0.w + b1.w + b2.w + b3.w;
        ((float4*)(out + (size_t)n * DD))[t] = o;
    }
}

// ---------------------------------------------------------------------------
extern "C" void kernel_launch(void* const* d_in, const int* in_sizes, int n_in,
                              void* d_out, int out_size)
{
    const float* x    = (const float*)d_in[0];
    const float* d    = (const float*)d_in[1];
    const float* d1   = (const float*)d_in[2];
    const float* d2   = (const float*)d_in[3];
    const int*   src  = (const int*)d_in[4];
    const int*   dst  = (const int*)d_in[5];
    const int*   cand = (const int*)d_in[6];
    const int*   split = (n_in >= 8) ? (const int*)d_in[7] : nullptr;
    float* out = (float*)d_out;

    (void)in_sizes; (void)out_size;

    // one-time host resources (no device memory involved)
    static cudaStream_t s2 = nullptr;
    static cudaEvent_t evA = nullptr, evB = nullptr;
    if (s2 == nullptr) {
        cudaStreamCreateWithFlags(&s2, cudaStreamNonBlocking);
        cudaEventCreateWithFlags(&evA, cudaEventDisableTiming);
        cudaEventCreateWithFlags(&evB, cudaEventDisableTiming);
    }

    // fork: convert_x on s2 concurrent with zero+bucket on the main stream
    cudaEventRecord(evA, 0);
    cudaStreamWaitEvent(s2, evA, 0);
    convert_x_kernel<<<((RR * NSRC * DD / 8) + 255) / 256, 256, 0, s2>>>(x);
    cudaEventRecord(evB, s2);

    zero_cnt_kernel<<<(RR * NN + 255) / 256, 256>>>();
    {
        dim3 grid((EE + 255) / 256, RR);
        bucket_kernel<<<grid, 256>>>(src, dst);
    }
    cudaStreamWaitEvent(0, evB, 0);   // join before agg

    agg_kernel<<<(RR * NN) / 8, 256>>>(d, d1, d2, split);
    mask_kernel<<<NN, 256>>>(cand, out);
}

// round 5
// speedup vs baseline: 2.1329x; 1.1278x over previous
#include <cuda_runtime.h>
#include <cuda_fp16.h>
#include <math.h>

// Problem constants (fixed instance)
#define RR   4
#define NN   20000
#define NSRC 20000
#define DD   256
#define EE   640000
#define KK   16
#define CAP  96

// Static scratch (allocation-free rule)
__device__ int            g_cnt[RR * NN];
__device__ unsigned short g_slots16[(size_t)RR * NN * CAP];
__device__ __half         g_H16[(size_t)NN * RR * DD];      // [N][R*D] fp16 (40MB)
__device__ __half         g_x16[(size_t)RR * NSRC * DD];    // fp16 x (40MB)

#define H2(u) (*(const __half2*)&(u))

// ---------------------------------------------------------------------------
// x (fp32) -> g_x16 (fp16); 8 floats per thread, 16B stores
__global__ void convert_x_kernel(const float* __restrict__ x) {
    size_t i = (size_t)blockIdx.x * blockDim.x + threadIdx.x;
    const size_t total = (size_t)RR * NSRC * DD / 8;
    if (i >= total) return;
    float4 v0 = ((const float4*)x)[2 * i];
    float4 v1 = ((const float4*)x)[2 * i + 1];
    __half2 h0 = __floats2half2_rn(v0.x, v0.y);
    __half2 h1 = __floats2half2_rn(v0.z, v0.w);
    __half2 h2 = __floats2half2_rn(v1.x, v1.y);
    __half2 h3 = __floats2half2_rn(v1.z, v1.w);
    uint4 packed;
    packed.x = *(const unsigned*)&h0;
    packed.y = *(const unsigned*)&h1;
    packed.z = *(const unsigned*)&h2;
    packed.w = *(const unsigned*)&h3;
    ((uint4*)g_x16)[i] = packed;
}

// 2 edges per thread via int2 loads
__global__ void bucket_kernel(const int* __restrict__ src_idx,
                              const int* __restrict__ dst_idx) {
    int e2 = blockIdx.x * blockDim.x + threadIdx.x;
    int r  = blockIdx.y;
    if (e2 >= EE / 2) return;
    int2 s2 = ((const int2*)(src_idx + (size_t)r * EE))[e2];
    int2 d2 = ((const int2*)(dst_idx + (size_t)r * EE))[e2];
    {
        int b = r * NN + d2.x;
        int rank = atomicAdd(&g_cnt[b], 1);
        if (rank < CAP) g_slots16[(size_t)b * CAP + rank] = (unsigned short)s2.x;
    }
    {
        int b = r * NN + d2.y;
        int rank = atomicAdd(&g_cnt[b], 1);
        if (rank < CAP) g_slots16[(size_t)b * CAP + rank] = (unsigned short)s2.y;
    }
}

// ---------------------------------------------------------------------------
// One WARP per (n, r). Warp-local softmax, then uint4 fp16 gather with
// half2 FMA accumulation flushed to fp32 every 4 edges.
__global__ __launch_bounds__(256) void agg_kernel(
    const float* __restrict__ d,    // [R, NSRC]
    const float* __restrict__ d1,
    const float* __restrict__ d2,
    const int*   __restrict__ split_p)
{
    const int warp = threadIdx.x >> 5;
    const int lane = threadIdx.x & 31;
    const int p = blockIdx.x * 8 + warp;
    const int n = p >> 2;
    const int g = p & 3;

    __shared__ __half2        swh[8][CAP];   // (w,w) per edge
    __shared__ unsigned short ssrc[8][CAP];

    int cnt = g_cnt[g * NN + n];
    if (cnt > CAP) cnt = CAP;

    const int split = split_p ? __ldg(split_p) : 10000;
    const bool use1 = (n < split);

    const unsigned short* slot = g_slots16 + ((size_t)g * NN + n) * CAP;

    float l[3];
    int   s[3];
    #pragma unroll
    for (int j = 0; j < 3; j++) {
        int i = lane + 32 * j;
        l[j] = -1e30f; s[j] = 0;
        if (i < cnt) {
            int sv = slot[i];
            s[j] = sv;
            float dv = d[g * NSRC + sv];
            l[j] = use1 ? (d1[g * NSRC + sv] / dv)
                        : (-d2[g * NSRC + sv] / dv);
        }
    }
    float m = fmaxf(fmaxf(l[0], l[1]), l[2]);
    #pragma unroll
    for (int o = 16; o; o >>= 1) m = fmaxf(m, __shfl_xor_sync(0xffffffffu, m, o));

    float e[3];
    float sum = 0.f;
    #pragma unroll
    for (int j = 0; j < 3; j++) {
        e[j] = (lane + 32 * j < cnt) ? __expf(l[j] - m) : 0.f;
        sum += e[j];
    }
    #pragma unroll
    for (int o = 16; o; o >>= 1) sum += __shfl_xor_sync(0xffffffffu, sum, o);
    const float winv = 1.f / fmaxf(sum, 1e-9f);

    #pragma unroll
    for (int j = 0; j < 3; j++) {
        int i = lane + 32 * j;
        if (i < cnt) {
            swh[warp][i]  = __float2half2_rn(e[j] * winv);   // (w,w)
            ssrc[warp][i] = (unsigned short)s[j];
        }
    }
    __syncwarp();

    // gather: row = 32 uint4; lane owns chunk `lane`
    const uint4* xr = (const uint4*)g_x16 + (size_t)g * NSRC * 32 + lane;
    float a0=0,a1=0,a2=0,a3=0,a4=0,a5=0,a6=0,a7=0;
    const __half2 z = __float2half2_rn(0.f);

    int i = 0;
    for (; i + 4 <= cnt; i += 4) {
        __half2 w0 = swh[warp][i],   w1 = swh[warp][i+1];
        __half2 w2 = swh[warp][i+2], w3 = swh[warp][i+3];
        uint4 u0 = xr[(size_t)ssrc[warp][i]   * 32];
        uint4 u1 = xr[(size_t)ssrc[warp][i+1] * 32];
        uint4 u2 = xr[(size_t)ssrc[warp][i+2] * 32];
        uint4 u3 = xr[(size_t)ssrc[warp][i+3] * 32];
        __half2 c0 = z, c1 = z, c2 = z, c3 = z;
        c0 = __hfma2(w0, H2(u0.x), c0); c1 = __hfma2(w0, H2(u0.y), c1);
        c2 = __hfma2(w0, H2(u0.z), c2); c3 = __hfma2(w0, H2(u0.w), c3);
        c0 = __hfma2(w1, H2(u1.x), c0); c1 = __hfma2(w1, H2(u1.y), c1);
        c2 = __hfma2(w1, H2(u1.z), c2); c3 = __hfma2(w1, H2(u1.w), c3);
        c0 = __hfma2(w2, H2(u2.x), c0); c1 = __hfma2(w2, H2(u2.y), c1);
        c2 = __hfma2(w2, H2(u2.z), c2); c3 = __hfma2(w2, H2(u2.w), c3);
        c0 = __hfma2(w3, H2(u3.x), c0); c1 = __hfma2(w3, H2(u3.y), c1);
        c2 = __hfma2(w3, H2(u3.z), c2); c3 = __hfma2(w3, H2(u3.w), c3);
        float2 f0 = __half22float2(c0), f1 = __half22float2(c1);
        float2 f2 = __half22float2(c2), f3 = __half22float2(c3);
        a0 += f0.x; a1 += f0.y; a2 += f1.x; a3 += f1.y;
        a4 += f2.x; a5 += f2.y; a6 += f3.x; a7 += f3.y;
    }
    for (; i < cnt; i++) {
        __half2 w0 = swh[warp][i];
        uint4 u0 = xr[(size_t)ssrc[warp][i] * 32];
        float2 f0 = __half22float2(__hmul2(w0, H2(u0.x)));
        float2 f1 = __half22float2(__hmul2(w0, H2(u0.y)));
        float2 f2 = __half22float2(__hmul2(w0, H2(u0.z)));
        float2 f3 = __half22float2(__hmul2(w0, H2(u0.w)));
        a0 += f0.x; a1 += f0.y; a2 += f1.x; a3 += f1.y;
        a4 += f2.x; a5 += f2.y; a6 += f3.x; a7 += f3.y;
    }

    __half2 h0 = __floats2half2_rn(a0, a1);
    __half2 h1 = __floats2half2_rn(a2, a3);
    __half2 h2 = __floats2half2_rn(a4, a5);
    __half2 h3 = __floats2half2_rn(a6, a7);
    uint4 packed;
    packed.x = *(const unsigned*)&h0;
    packed.y = *(const unsigned*)&h1;
    packed.z = *(const unsigned*)&h2;
    packed.w = *(const unsigned*)&h3;
    ((uint4*)(g_H16 + ((size_t)n * RR + g) * DD))[lane] = packed;
}

// ---------------------------------------------------------------------------
// One block per node. Thread t owns 4 elems (uint2) of the flattened [R*D]=1024.
// Squared diffs kept in registers as half2; candidate distances reduced as
// half2 pairs (2 candidates per shuffle chain); s-accumulation in fp32.
__global__ __launch_bounds__(256) void mask_kernel(
    const int* __restrict__ cand,   // [N, K]
    float*     __restrict__ out)    // [N, D]
{
    const int n = blockIdx.x;
    const int t = threadIdx.x;
    const int lane = t & 31, w = t >> 5;

    __shared__ int     scand[KK];
    __shared__ __half  wsumh[8][KK];    // per-warp partial dist^2 (fp16)
    __shared__ float   satt[KK];
    __shared__ float   sval[RR * DD];

    if (t < KK) scand[t] = cand[n * KK + t];
    __syncthreads();

    const uint2 ownu = ((const uint2*)(g_H16 + (size_t)n * (RR * DD)))[t];
    const __half2 own0 = H2(ownu.x);
    const __half2 own1 = H2(ownu.y);

    __half2 sq0[KK], sq1[KK];
    __half2 ph[KK];
    #pragma unroll
    for (int k = 0; k < KK; k++) {
        uint2 cu = ((const uint2*)(g_H16 + (size_t)scand[k] * (RR * DD)))[t];
        __half2 d0 = __hsub2(own0, H2(cu.x));
        __half2 d1 = __hsub2(own1, H2(cu.y));
        __half2 q0 = __hmul2(d0, d0);
        __half2 q1 = __hmul2(d1, d1);
        sq0[k] = q0; sq1[k] = q1;
        ph[k] = __hadd2(q0, q1);
    }

    // pair candidates: pp[j] = ( p[2j], p[2j+1] ) as half2
    __half2 pp[KK / 2];
    #pragma unroll
    for (int j = 0; j < KK / 2; j++) {
        __half a = __hadd(__low2half(ph[2*j]),     __high2half(ph[2*j]));
        __half b = __hadd(__low2half(ph[2*j + 1]), __high2half(ph[2*j + 1]));
        pp[j] = __halves2half2(a, b);
    }
    #pragma unroll
    for (int j = 0; j < KK / 2; j++) {
        unsigned v = *(unsigned*)&pp[j];
        #pragma unroll
        for (int o = 16; o; o >>= 1) {
            unsigned u = __shfl_xor_sync(0xffffffffu, v, o);
            __half2 hv = __hadd2(*(__half2*)&v, *(__half2*)&u);
            v = *(unsigned*)&hv;
        }
        if (lane == 0) ((__half2*)&wsumh[w][0])[j] = *(__half2*)&v;
    }
    __syncthreads();

    if (t < 32) {
        float dist = 1e30f;
        if (t < KK) {
            float s = 0.f;
            #pragma unroll
            for (int ww = 0; ww < 8; ww++) s += __half2float(wsumh[ww][t]);
            dist = sqrtf(s);
        }
        float mn = dist;
        #pragma unroll
        for (int o = 16; o; o >>= 1) mn = fminf(mn, __shfl_xor_sync(0xffffffffu, mn, o));
        float e = (t < KK) ? __expf(mn - dist) : 0.f;
        float s = e;
        #pragma unroll
        for (int o = 16; o; o >>= 1) s += __shfl_xor_sync(0xffffffffu, s, o);
        if (t < KK) satt[t] = e / s;
    }
    __syncthreads();

    float sx = 0.f, sy = 0.f, sz = 0.f, sw_ = 0.f;
    #pragma unroll
    for (int k = 0; k < KK; k++) {
        float a = satt[k];
        float2 f0 = __half22float2(sq0[k]);
        float2 f1 = __half22float2(sq1[k]);
        sx  += a * f0.x;
        sy  += a * f0.y;
        sz  += a * f1.x;
        sw_ += a * f1.y;
    }
    float2 o0 = __half22float2(own0);
    float2 o1 = __half22float2(own1);
    float4 val;
    val.x = o0.x * __expf(-sx);
    val.y = o0.y * __expf(-sy);
    val.z = o1.x * __expf(-sz);
    val.w = o1.y * __expf(-sw_);
    ((float4*)sval)[t] = val;
    __syncthreads();

    if (t < 64) {
        float4 b0 = ((float4*)sval)[t];
        float4 b1 = ((float4*)sval)[t + 64];
        float4 b2 = ((float4*)sval)[t + 128];
        float4 b3 = ((float4*)sval)[t + 192];
        float4 o;
        o.x = b0.x + b1.x + b2.x + b3.x;
        o.y = b0.y + b1.y + b2.y + b3.y;
        o.z = b0.z + b1.z + b2.z + b3.z;
        o.w = b0.w + b1.w + b2.w + b3.w;
        ((float4*)(out + (size_t)n * DD))[t] = o;
    }
}

// ---------------------------------------------------------------------------
extern "C" void kernel_launch(void* const* d_in, const int* in_sizes, int n_in,
                              void* d_out, int out_size)
{
    const float* x    = (const float*)d_in[0];
    const float* d    = (const float*)d_in[1];
    const float* d1   = (const float*)d_in[2];
    const float* d2   = (const float*)d_in[3];
    const int*   src  = (const int*)d_in[4];
    const int*   dst  = (const int*)d_in[5];
    const int*   cand = (const int*)d_in[6];
    const int*   split = (n_in >= 8) ? (const int*)d_in[7] : nullptr;
    float* out = (float*)d_out;

    (void)in_sizes; (void)out_size;

    static cudaStream_t s2 = nullptr;
    static cudaEvent_t evA = nullptr, evB = nullptr;
    static void* cnt_ptr = nullptr;
    if (s2 == nullptr) {
        cudaStreamCreateWithFlags(&s2, cudaStreamNonBlocking);
        cudaEventCreateWithFlags(&evA, cudaEventDisableTiming);
        cudaEventCreateWithFlags(&evB, cudaEventDisableTiming);
        cudaGetSymbolAddress(&cnt_ptr, g_cnt);
    }

    // fork: convert_x on s2 concurrent with zero+bucket on main stream
    cudaEventRecord(evA, 0);
    cudaStreamWaitEvent(s2, evA, 0);
    convert_x_kernel<<<((RR * NSRC * DD / 8) + 255) / 256, 256, 0, s2>>>(x);
    cudaEventRecord(evB, s2);

    cudaMemsetAsync(cnt_ptr, 0, (size_t)RR * NN * sizeof(int), 0);
    {
        dim3 grid((EE / 2 + 255) / 256, RR);
        bucket_kernel<<<grid, 256>>>(src, dst);
    }
    cudaStreamWaitEvent(0, evB, 0);   // join before agg

    agg_kernel<<<(RR * NN) / 8, 256>>>(d, d1, d2, split);
    mask_kernel<<<NN, 256>>>(cand, out);
}

// round 6
// speedup vs baseline: 2.2692x; 1.0639x over previous
#include <cuda_runtime.h>
#include <cuda_fp16.h>
#include <math.h>

// Problem constants (fixed instance)
#define RR   4
#define NN   20000
#define NSRC 20000
#define DD   256
#define EE   640000
#define KK   16
#define CAP  96

// Static scratch (allocation-free rule)
__device__ int            g_cnt[RR * NN];
__device__ unsigned short g_slots16[(size_t)RR * NN * CAP];
__device__ __half         g_H16[(size_t)NN * RR * DD];      // [N][R*D] fp16 (40MB)
__device__ __half         g_x16[(size_t)RR * NSRC * DD];    // fp16 x (40MB)

#define H2(u) (*(const __half2*)&(u))

// ---------------------------------------------------------------------------
// Fused prep: convert blocks (role 0,1) stream x->fp16; bucket blocks (role 2)
// scatter edges into per-(r,dst) slots. 2:1 interleave keeps both resident.
#define CONV_BLOCKS 10000   // 2.56M uint4-groups / 256
#define BUCK_BLOCKS 5000    // 1.28M edge-pairs / 256
__global__ __launch_bounds__(256) void prep_kernel(
    const float* __restrict__ x,
    const int*   __restrict__ src_idx,
    const int*   __restrict__ dst_idx)
{
    const int bx = blockIdx.x;
    const int role = bx % 3;
    if (role != 2) {
        // convert: conv_id = bx - (#bucket blocks before bx)
        int conv_id = bx - (bx + 1) / 3;
        size_t i = (size_t)conv_id * 256 + threadIdx.x;   // group of 8 floats
        float4 v0 = ((const float4*)x)[2 * i];
        float4 v1 = ((const float4*)x)[2 * i + 1];
        __half2 h0 = __floats2half2_rn(v0.x, v0.y);
        __half2 h1 = __floats2half2_rn(v0.z, v0.w);
        __half2 h2 = __floats2half2_rn(v1.x, v1.y);
        __half2 h3 = __floats2half2_rn(v1.z, v1.w);
        uint4 packed;
        packed.x = *(const unsigned*)&h0;
        packed.y = *(const unsigned*)&h1;
        packed.z = *(const unsigned*)&h2;
        packed.w = *(const unsigned*)&h3;
        ((uint4*)g_x16)[i] = packed;
    } else {
        int e2g = (bx / 3) * 256 + threadIdx.x;           // global edge-pair id
        int r   = e2g / (EE / 2);
        int e2  = e2g - r * (EE / 2);
        int2 s2 = ((const int2*)(src_idx + (size_t)r * EE))[e2];
        int2 d2 = ((const int2*)(dst_idx + (size_t)r * EE))[e2];
        {
            int b = r * NN + d2.x;
            int rank = atomicAdd(&g_cnt[b], 1);
            if (rank < CAP) g_slots16[(size_t)b * CAP + rank] = (unsigned short)s2.x;
        }
        {
            int b = r * NN + d2.y;
            int rank = atomicAdd(&g_cnt[b], 1);
            if (rank < CAP) g_slots16[(size_t)b * CAP + rank] = (unsigned short)s2.y;
        }
    }
}

// ---------------------------------------------------------------------------
// One WARP per (n, r). Warp-local softmax, then uint4 fp16 gather with
// half2 FMA accumulation flushed to fp32 every 4 edges.
__global__ __launch_bounds__(256) void agg_kernel(
    const float* __restrict__ d,    // [R, NSRC]
    const float* __restrict__ d1,
    const float* __restrict__ d2,
    const int*   __restrict__ split_p)
{
    const int warp = threadIdx.x >> 5;
    const int lane = threadIdx.x & 31;
    const int p = blockIdx.x * 8 + warp;
    const int n = p >> 2;
    const int g = p & 3;

    __shared__ __half2        swh[8][CAP];   // (w,w) per edge
    __shared__ unsigned short ssrc[8][CAP];

    int cnt = g_cnt[g * NN + n];
    if (cnt > CAP) cnt = CAP;

    const int split = split_p ? __ldg(split_p) : 10000;
    const bool use1 = (n < split);

    const unsigned short* slot = g_slots16 + ((size_t)g * NN + n) * CAP;

    float l[3];
    int   s[3];
    #pragma unroll
    for (int j = 0; j < 3; j++) {
        int i = lane + 32 * j;
        l[j] = -1e30f; s[j] = 0;
        if (i < cnt) {
            int sv = slot[i];
            s[j] = sv;
            float dv = d[g * NSRC + sv];
            l[j] = use1 ? (d1[g * NSRC + sv] / dv)
                        : (-d2[g * NSRC + sv] / dv);
        }
    }
    float m = fmaxf(fmaxf(l[0], l[1]), l[2]);
    #pragma unroll
    for (int o = 16; o; o >>= 1) m = fmaxf(m, __shfl_xor_sync(0xffffffffu, m, o));

    float e[3];
    float sum = 0.f;
    #pragma unroll
    for (int j = 0; j < 3; j++) {
        e[j] = (lane + 32 * j < cnt) ? __expf(l[j] - m) : 0.f;
        sum += e[j];
    }
    #pragma unroll
    for (int o = 16; o; o >>= 1) sum += __shfl_xor_sync(0xffffffffu, sum, o);
    const float winv = 1.f / fmaxf(sum, 1e-9f);

    #pragma unroll
    for (int j = 0; j < 3; j++) {
        int i = lane + 32 * j;
        if (i < cnt) {
            swh[warp][i]  = __float2half2_rn(e[j] * winv);
            ssrc[warp][i] = (unsigned short)s[j];
        }
    }
    __syncwarp();

    const uint4* xr = (const uint4*)g_x16 + (size_t)g * NSRC * 32 + lane;
    float a0=0,a1=0,a2=0,a3=0,a4=0,a5=0,a6=0,a7=0;
    const __half2 z = __float2half2_rn(0.f);

    int i = 0;
    for (; i + 4 <= cnt; i += 4) {
        __half2 w0 = swh[warp][i],   w1 = swh[warp][i+1];
        __half2 w2 = swh[warp][i+2], w3 = swh[warp][i+3];
        uint4 u0 = xr[(size_t)ssrc[warp][i]   * 32];
        uint4 u1 = xr[(size_t)ssrc[warp][i+1] * 32];
        uint4 u2 = xr[(size_t)ssrc[warp][i+2] * 32];
        uint4 u3 = xr[(size_t)ssrc[warp][i+3] * 32];
        __half2 c0 = z, c1 = z, c2 = z, c3 = z;
        c0 = __hfma2(w0, H2(u0.x), c0); c1 = __hfma2(w0, H2(u0.y), c1);
        c2 = __hfma2(w0, H2(u0.z), c2); c3 = __hfma2(w0, H2(u0.w), c3);
        c0 = __hfma2(w1, H2(u1.x), c0); c1 = __hfma2(w1, H2(u1.y), c1);
        c2 = __hfma2(w1, H2(u1.z), c2); c3 = __hfma2(w1, H2(u1.w), c3);
        c0 = __hfma2(w2, H2(u2.x), c0); c1 = __hfma2(w2, H2(u2.y), c1);
        c2 = __hfma2(w2, H2(u2.z), c2); c3 = __hfma2(w2, H2(u2.w), c3);
        c0 = __hfma2(w3, H2(u3.x), c0); c1 = __hfma2(w3, H2(u3.y), c1);
        c2 = __hfma2(w3, H2(u3.z), c2); c3 = __hfma2(w3, H2(u3.w), c3);
        float2 f0 = __half22float2(c0), f1 = __half22float2(c1);
        float2 f2 = __half22float2(c2), f3 = __half22float2(c3);
        a0 += f0.x; a1 += f0.y; a2 += f1.x; a3 += f1.y;
        a4 += f2.x; a5 += f2.y; a6 += f3.x; a7 += f3.y;
    }
    for (; i < cnt; i++) {
        __half2 w0 = swh[warp][i];
        uint4 u0 = xr[(size_t)ssrc[warp][i] * 32];
        float2 f0 = __half22float2(__hmul2(w0, H2(u0.x)));
        float2 f1 = __half22float2(__hmul2(w0, H2(u0.y)));
        float2 f2 = __half22float2(__hmul2(w0, H2(u0.z)));
        float2 f3 = __half22float2(__hmul2(w0, H2(u0.w)));
        a0 += f0.x; a1 += f0.y; a2 += f1.x; a3 += f1.y;
        a4 += f2.x; a5 += f2.y; a6 += f3.x; a7 += f3.y;
    }

    __half2 h0 = __floats2half2_rn(a0, a1);
    __half2 h1 = __floats2half2_rn(a2, a3);
    __half2 h2 = __floats2half2_rn(a4, a5);
    __half2 h3 = __floats2half2_rn(a6, a7);
    uint4 packed;
    packed.x = *(const unsigned*)&h0;
    packed.y = *(const unsigned*)&h1;
    packed.z = *(const unsigned*)&h2;
    packed.w = *(const unsigned*)&h3;
    ((uint4*)(g_H16 + ((size_t)n * RR + g) * DD))[lane] = packed;
}

// ---------------------------------------------------------------------------
// One block per node. Thread t owns 4 elems (uint2). Squared diffs in regs as
// half2; s-accumulation in half2 with split partials merged in fp32.
__global__ __launch_bounds__(256) void mask_kernel(
    const int* __restrict__ cand,   // [N, K]
    float*     __restrict__ out)    // [N, D]
{
    const int n = blockIdx.x;
    const int t = threadIdx.x;
    const int lane = t & 31, w = t >> 5;

    __shared__ int     scand[KK];
    __shared__ __half  wsumh[8][KK];
    __shared__ __half2 satth[KK];
    __shared__ float   sval[RR * DD];

    if (t < KK) scand[t] = cand[n * KK + t];
    __syncthreads();

    const uint2 ownu = ((const uint2*)(g_H16 + (size_t)n * (RR * DD)))[t];
    const __half2 own0 = H2(ownu.x);
    const __half2 own1 = H2(ownu.y);

    __half2 sq0[KK], sq1[KK];
    __half2 ph[KK];
    #pragma unroll
    for (int k = 0; k < KK; k++) {
        uint2 cu = ((const uint2*)(g_H16 + (size_t)scand[k] * (RR * DD)))[t];
        __half2 d0 = __hsub2(own0, H2(cu.x));
        __half2 d1 = __hsub2(own1, H2(cu.y));
        __half2 q0 = __hmul2(d0, d0);
        __half2 q1 = __hmul2(d1, d1);
        sq0[k] = q0; sq1[k] = q1;
        ph[k] = __hadd2(q0, q1);
    }

    // pair candidates: pp[j] = ( p[2j], p[2j+1] ) as half2
    __half2 pp[KK / 2];
    #pragma unroll
    for (int j = 0; j < KK / 2; j++) {
        __half a = __hadd(__low2half(ph[2*j]),     __high2half(ph[2*j]));
        __half b = __hadd(__low2half(ph[2*j + 1]), __high2half(ph[2*j + 1]));
        pp[j] = __halves2half2(a, b);
    }
    #pragma unroll
    for (int j = 0; j < KK / 2; j++) {
        unsigned v = *(unsigned*)&pp[j];
        #pragma unroll
        for (int o = 16; o; o >>= 1) {
            unsigned u = __shfl_xor_sync(0xffffffffu, v, o);
            __half2 hv = __hadd2(*(__half2*)&v, *(__half2*)&u);
            v = *(unsigned*)&hv;
        }
        if (lane == 0) ((__half2*)&wsumh[w][0])[j] = *(__half2*)&v;
    }
    __syncthreads();

    if (t < 32) {
        float dist = 1e30f;
        if (t < KK) {
            float s = 0.f;
            #pragma unroll
            for (int ww = 0; ww < 8; ww++) s += __half2float(wsumh[ww][t]);
            dist = sqrtf(s);
        }
        float mn = dist;
        #pragma unroll
        for (int o = 16; o; o >>= 1) mn = fminf(mn, __shfl_xor_sync(0xffffffffu, mn, o));
        float e = (t < KK) ? __expf(mn - dist) : 0.f;
        float s = e;
        #pragma unroll
        for (int o = 16; o; o >>= 1) s += __shfl_xor_sync(0xffffffffu, s, o);
        if (t < KK) satth[t] = __float2half2_rn(e / s);
    }
    __syncthreads();

    // s_e = sum_k att_k * q_k[e] in half2, two 8-term partials merged in fp32
    const __half2 z = __float2half2_rn(0.f);
    __half2 pa0 = z, pa1 = z, pb0 = z, pb1 = z;
    #pragma unroll
    for (int k = 0; k < 8; k++) {
        __half2 a = satth[k];
        pa0 = __hfma2(a, sq0[k], pa0);
        pa1 = __hfma2(a, sq1[k], pa1);
    }
    #pragma unroll
    for (int k = 8; k < KK; k++) {
        __half2 a = satth[k];
        pb0 = __hfma2(a, sq0[k], pb0);
        pb1 = __hfma2(a, sq1[k], pb1);
    }
    float2 fa0 = __half22float2(pa0), fb0 = __half22float2(pb0);
    float2 fa1 = __half22float2(pa1), fb1 = __half22float2(pb1);
    float sx = fa0.x + fb0.x, sy = fa0.y + fb0.y;
    float sz = fa1.x + fb1.x, sw_ = fa1.y + fb1.y;

    float2 o0 = __half22float2(own0);
    float2 o1 = __half22float2(own1);
    float4 val;
    val.x = o0.x * __expf(-sx);
    val.y = o0.y * __expf(-sy);
    val.z = o1.x * __expf(-sz);
    val.w = o1.y * __expf(-sw_);
    ((float4*)sval)[t] = val;
    __syncthreads();

    if (t < 64) {
        float4 b0 = ((float4*)sval)[t];
        float4 b1 = ((float4*)sval)[t + 64];
        float4 b2 = ((float4*)sval)[t + 128];
        float4 b3 = ((float4*)sval)[t + 192];
        float4 o;
        o.x = b0.x + b1.x + b2.x + b3.x;
        o.y = b0.y + b1.y + b2.y + b3.y;
        o.z = b0.z + b1.z + b2.z + b3.z;
        o.w = b0.w + b1.w + b2.w + b3.w;
        ((float4*)(out + (size_t)n * DD))[t] = o;
    }
}

// ---------------------------------------------------------------------------
extern "C" void kernel_launch(void* const* d_in, const int* in_sizes, int n_in,
                              void* d_out, int out_size)
{
    const float* x    = (const float*)d_in[0];
    const float* d    = (const float*)d_in[1];
    const float* d1   = (const float*)d_in[2];
    const float* d2   = (const float*)d_in[3];
    const int*   src  = (const int*)d_in[4];
    const int*   dst  = (const int*)d_in[5];
    const int*   cand = (const int*)d_in[6];
    const int*   split = (n_in >= 8) ? (const int*)d_in[7] : nullptr;
    float* out = (float*)d_out;

    (void)in_sizes; (void)out_size;

    static void* cnt_ptr = nullptr;
    if (cnt_ptr == nullptr) cudaGetSymbolAddress(&cnt_ptr, g_cnt);

    cudaMemsetAsync(cnt_ptr, 0, (size_t)RR * NN * sizeof(int), 0);
    prep_kernel<<<CONV_BLOCKS + BUCK_BLOCKS, 256>>>(x, src, dst);
    agg_kernel<<<(RR * NN) / 8, 256>>>(d, d1, d2, split);
    mask_kernel<<<NN, 256>>>(cand, out);
}

// round 7
// speedup vs baseline: 2.2861x; 1.0075x over previous
#include <cuda_runtime.h>
#include <cuda_fp16.h>
#include <math.h>

// Problem constants (fixed instance)
#define RR   4
#define NN   20000
#define NSRC 20000
#define DD   256
#define EE   640000
#define KK   16
#define CAP  96

// Static scratch (allocation-free rule)
__device__ int            g_cnt[RR * NN];
__device__ unsigned short g_slots16[(size_t)RR * NN * CAP];
__device__ __half         g_H16[(size_t)NN * RR * DD];      // [N][R*D] fp16 (40MB)
__device__ __half         g_x16[(size_t)RR * NSRC * DD];    // fp16 x (40MB)

#define H2(u) (*(const __half2*)&(u))

// ---------------------------------------------------------------------------
// Fused prep, 1:1 interleave. Even blocks: convert x -> fp16 (10000 blocks).
// Odd blocks: bucket one edge per thread (10000 blocks, 2.56M edges).
__global__ __launch_bounds__(256) void prep_kernel(
    const float* __restrict__ x,
    const int*   __restrict__ src_idx,
    const int*   __restrict__ dst_idx)
{
    const int bx = blockIdx.x;
    if ((bx & 1) == 0) {
        size_t i = (size_t)(bx >> 1) * 256 + threadIdx.x;   // group of 8 floats
        float4 v0 = ((const float4*)x)[2 * i];
        float4 v1 = ((const float4*)x)[2 * i + 1];
        __half2 h0 = __floats2half2_rn(v0.x, v0.y);
        __half2 h1 = __floats2half2_rn(v0.z, v0.w);
        __half2 h2 = __floats2half2_rn(v1.x, v1.y);
        __half2 h3 = __floats2half2_rn(v1.z, v1.w);
        uint4 packed;
        packed.x = *(const unsigned*)&h0;
        packed.y = *(const unsigned*)&h1;
        packed.z = *(const unsigned*)&h2;
        packed.w = *(const unsigned*)&h3;
        ((uint4*)g_x16)[i] = packed;
    } else {
        int e = (bx >> 1) * 256 + threadIdx.x;   // global edge id in [0, R*E)
        int s   = src_idx[e];
        int dst = dst_idx[e];
        int r   = (int)(((long long)e * 0x6B5FCA6BLL) >> 62 >> 0);  // fallback-safe? use div
        r = e / EE;                               // compiler emits mul-high
        int b = r * NN + dst;
        int rank = atomicAdd(&g_cnt[b], 1);
        if (rank < CAP) g_slots16[(size_t)b * CAP + rank] = (unsigned short)s;
    }
}

// ---------------------------------------------------------------------------
// One WARP per (n, r). Warp-local softmax; gather uses precomputed u32 row
// offsets (src*32 uint4 units) and half2 FMA accumulation, fp32 flush per 4.
__global__ __launch_bounds__(256) void agg_kernel(
    const float* __restrict__ d,    // [R, NSRC]
    const float* __restrict__ d1,
    const float* __restrict__ d2,
    const int*   __restrict__ split_p)
{
    const int warp = threadIdx.x >> 5;
    const int lane = threadIdx.x & 31;
    const int p = blockIdx.x * 8 + warp;
    const int n = p >> 2;
    const int g = p & 3;

    __shared__ __half2  swh[8][CAP];    // (w,w) per edge
    __shared__ unsigned soff[8][CAP];   // src*32 (uint4 row offset)

    int cnt = g_cnt[g * NN + n];
    if (cnt > CAP) cnt = CAP;

    const int split = split_p ? __ldg(split_p) : 10000;
    const bool use1 = (n < split);

    const unsigned short* slot = g_slots16 + ((size_t)g * NN + n) * CAP;

    float l[3];
    int   s[3];
    #pragma unroll
    for (int j = 0; j < 3; j++) {
        int i = lane + 32 * j;
        l[j] = -1e30f; s[j] = 0;
        if (i < cnt) {
            int sv = slot[i];
            s[j] = sv;
            float dv = d[g * NSRC + sv];
            l[j] = use1 ? (d1[g * NSRC + sv] / dv)
                        : (-d2[g * NSRC + sv] / dv);
        }
    }
    float m = fmaxf(fmaxf(l[0], l[1]), l[2]);
    #pragma unroll
    for (int o = 16; o; o >>= 1) m = fmaxf(m, __shfl_xor_sync(0xffffffffu, m, o));

    float e[3];
    float sum = 0.f;
    #pragma unroll
    for (int j = 0; j < 3; j++) {
        e[j] = (lane + 32 * j < cnt) ? __expf(l[j] - m) : 0.f;
        sum += e[j];
    }
    #pragma unroll
    for (int o = 16; o; o >>= 1) sum += __shfl_xor_sync(0xffffffffu, sum, o);
    const float winv = 1.f / fmaxf(sum, 1e-9f);

    #pragma unroll
    for (int j = 0; j < 3; j++) {
        int i = lane + 32 * j;
        if (i < cnt) {
            swh[warp][i]  = __float2half2_rn(e[j] * winv);
            soff[warp][i] = (unsigned)s[j] * 32u;
        }
    }
    __syncwarp();

    const uint4* xr = (const uint4*)g_x16 + (size_t)g * NSRC * 32 + lane;
    float a0=0,a1=0,a2=0,a3=0,a4=0,a5=0,a6=0,a7=0;
    const __half2 z = __float2half2_rn(0.f);

    int i = 0;
    for (; i + 4 <= cnt; i += 4) {
        __half2 w0 = swh[warp][i],   w1 = swh[warp][i+1];
        __half2 w2 = swh[warp][i+2], w3 = swh[warp][i+3];
        uint4 u0 = xr[soff[warp][i]];
        uint4 u1 = xr[soff[warp][i+1]];
        uint4 u2 = xr[soff[warp][i+2]];
        uint4 u3 = xr[soff[warp][i+3]];
        __half2 c0 = z, c1 = z, c2 = z, c3 = z;
        c0 = __hfma2(w0, H2(u0.x), c0); c1 = __hfma2(w0, H2(u0.y), c1);
        c2 = __hfma2(w0, H2(u0.z), c2); c3 = __hfma2(w0, H2(u0.w), c3);
        c0 = __hfma2(w1, H2(u1.x), c0); c1 = __hfma2(w1, H2(u1.y), c1);
        c2 = __hfma2(w1, H2(u1.z), c2); c3 = __hfma2(w1, H2(u1.w), c3);
        c0 = __hfma2(w2, H2(u2.x), c0); c1 = __hfma2(w2, H2(u2.y), c1);
        c2 = __hfma2(w2, H2(u2.z), c2); c3 = __hfma2(w2, H2(u2.w), c3);
        c0 = __hfma2(w3, H2(u3.x), c0); c1 = __hfma2(w3, H2(u3.y), c1);
        c2 = __hfma2(w3, H2(u3.z), c2); c3 = __hfma2(w3, H2(u3.w), c3);
        float2 f0 = __half22float2(c0), f1 = __half22float2(c1);
        float2 f2 = __half22float2(c2), f3 = __half22float2(c3);
        a0 += f0.x; a1 += f0.y; a2 += f1.x; a3 += f1.y;
        a4 += f2.x; a5 += f2.y; a6 += f3.x; a7 += f3.y;
    }
    for (; i < cnt; i++) {
        __half2 w0 = swh[warp][i];
        uint4 u0 = xr[soff[warp][i]];
        float2 f0 = __half22float2(__hmul2(w0, H2(u0.x)));
        float2 f1 = __half22float2(__hmul2(w0, H2(u0.y)));
        float2 f2 = __half22float2(__hmul2(w0, H2(u0.z)));
        float2 f3 = __half22float2(__hmul2(w0, H2(u0.w)));
        a0 += f0.x; a1 += f0.y; a2 += f1.x; a3 += f1.y;
        a4 += f2.x; a5 += f2.y; a6 += f3.x; a7 += f3.y;
    }

    __half2 h0 = __floats2half2_rn(a0, a1);
    __half2 h1 = __floats2half2_rn(a2, a3);
    __half2 h2 = __floats2half2_rn(a4, a5);
    __half2 h3 = __floats2half2_rn(a6, a7);
    uint4 packed;
    packed.x = *(const unsigned*)&h0;
    packed.y = *(const unsigned*)&h1;
    packed.z = *(const unsigned*)&h2;
    packed.w = *(const unsigned*)&h3;
    ((uint4*)(g_H16 + ((size_t)n * RR + g) * DD))[lane] = packed;
}

// ---------------------------------------------------------------------------
// One block per node. Thread t owns 4 elems (uint2). Squared diffs in regs as
// half2; s-accum in half2 split partials merged in fp32. 32-bit H indexing.
__global__ __launch_bounds__(256) void mask_kernel(
    const int* __restrict__ cand,   // [N, K]
    float*     __restrict__ out)    // [N, D]
{
    const int n = blockIdx.x;
    const int t = threadIdx.x;
    const int lane = t & 31, w = t >> 5;

    __shared__ unsigned coff[KK];       // cand*256 (uint2 row offset)
    __shared__ __half   wsumh[8][KK];
    __shared__ __half2  satth[KK];
    __shared__ float    sval[RR * DD];

    if (t < KK) coff[t] = (unsigned)cand[n * KK + t] * 256u;
    __syncthreads();

    const uint2* Hb = (const uint2*)g_H16 + t;   // row = 256 uint2
    const uint2 ownu = Hb[(unsigned)n * 256u];
    const __half2 own0 = H2(ownu.x);
    const __half2 own1 = H2(ownu.y);

    __half2 sq0[KK], sq1[KK];
    __half2 ph[KK];
    #pragma unroll
    for (int k = 0; k < KK; k++) {
        uint2 cu = Hb[coff[k]];
        __half2 d0 = __hsub2(own0, H2(cu.x));
        __half2 d1 = __hsub2(own1, H2(cu.y));
        __half2 q0 = __hmul2(d0, d0);
        __half2 q1 = __hmul2(d1, d1);
        sq0[k] = q0; sq1[k] = q1;
        ph[k] = __hadd2(q0, q1);
    }

    __half2 pp[KK / 2];
    #pragma unroll
    for (int j = 0; j < KK / 2; j++) {
        __half a = __hadd(__low2half(ph[2*j]),     __high2half(ph[2*j]));
        __half b = __hadd(__low2half(ph[2*j + 1]), __high2half(ph[2*j + 1]));
        pp[j] = __halves2half2(a, b);
    }
    #pragma unroll
    for (int j = 0; j < KK / 2; j++) {
        unsigned v = *(unsigned*)&pp[j];
        #pragma unroll
        for (int o = 16; o; o >>= 1) {
            unsigned u = __shfl_xor_sync(0xffffffffu, v, o);
            __half2 hv = __hadd2(*(__half2*)&v, *(__half2*)&u);
            v = *(unsigned*)&hv;
        }
        if (lane == 0) ((__half2*)&wsumh[w][0])[j] = *(__half2*)&v;
    }
    __syncthreads();

    if (t < 32) {
        float dist = 1e30f;
        if (t < KK) {
            float s = 0.f;
            #pragma unroll
            for (int ww = 0; ww < 8; ww++) s += __half2float(wsumh[ww][t]);
            dist = sqrtf(s);
        }
        float mn = dist;
        #pragma unroll
        for (int o = 16; o; o >>= 1) mn = fminf(mn, __shfl_xor_sync(0xffffffffu, mn, o));
        float e = (t < KK) ? __expf(mn - dist) : 0.f;
        float s = e;
        #pragma unroll
        for (int o = 16; o; o >>= 1) s += __shfl_xor_sync(0xffffffffu, s, o);
        if (t < KK) satth[t] = __float2half2_rn(e / s);
    }
    __syncthreads();

    const __half2 z = __float2half2_rn(0.f);
    __half2 pa0 = z, pa1 = z, pb0 = z, pb1 = z;
    #pragma unroll
    for (int k = 0; k < 8; k++) {
        __half2 a = satth[k];
        pa0 = __hfma2(a, sq0[k], pa0);
        pa1 = __hfma2(a, sq1[k], pa1);
    }
    #pragma unroll
    for (int k = 8; k < KK; k++) {
        __half2 a = satth[k];
        pb0 = __hfma2(a, sq0[k], pb0);
        pb1 = __hfma2(a, sq1[k], pb1);
    }
    float2 fa0 = __half22float2(pa0), fb0 = __half22float2(pb0);
    float2 fa1 = __half22float2(pa1), fb1 = __half22float2(pb1);
    float sx = fa0.x + fb0.x, sy = fa0.y + fb0.y;
    float sz = fa1.x + fb1.x, sw_ = fa1.y + fb1.y;

    float2 o0 = __half22float2(own0);
    float2 o1 = __half22float2(own1);
    float4 val;
    val.x = o0.x * __expf(-sx);
    val.y = o0.y * __expf(-sy);
    val.z = o1.x * __expf(-sz);
    val.w = o1.y * __expf(-sw_);
    ((float4*)sval)[t] = val;
    __syncthreads();

    if (t < 64) {
        float4 b0 = ((float4*)sval)[t];
        float4 b1 = ((float4*)sval)[t + 64];
        float4 b2 = ((float4*)sval)[t + 128];
        float4 b3 = ((float4*)sval)[t + 192];
        float4 o;
        o.x = b0.x + b1.x + b2.x + b3.x;
        o.y = b0.y + b1.y + b2.y + b3.y;
        o.z = b0.z + b1.z + b2.z + b3.z;
        o.w = b0.w + b1.w + b2.w + b3.w;
        ((float4*)(out + (size_t)n * DD))[t] = o;
    }
}

// ---------------------------------------------------------------------------
extern "C" void kernel_launch(void* const* d_in, const int* in_sizes, int n_in,
                              void* d_out, int out_size)
{
    const float* x    = (const float*)d_in[0];
    const float* d    = (const float*)d_in[1];
    const float* d1   = (const float*)d_in[2];
    const float* d2   = (const float*)d_in[3];
    const int*   src  = (const int*)d_in[4];
    const int*   dst  = (const int*)d_in[5];
    const int*   cand = (const int*)d_in[6];
    const int*   split = (n_in >= 8) ? (const int*)d_in[7] : nullptr;
    float* out = (float*)d_out;

    (void)in_sizes; (void)out_size;

    static void* cnt_ptr = nullptr;
    if (cnt_ptr == nullptr) cudaGetSymbolAddress(&cnt_ptr, g_cnt);

    cudaMemsetAsync(cnt_ptr, 0, (size_t)RR * NN * sizeof(int), 0);
    prep_kernel<<<20000, 256>>>(x, src, dst);
    agg_kernel<<<(RR * NN) / 8, 256>>>(d, d1, d2, split);
    mask_kernel<<<NN, 256>>>(cand, out);
}

// round 8
// speedup vs baseline: 2.3506x; 1.0282x over previous
#include <cuda_runtime.h>
#include <cuda_fp16.h>
#include <math.h>

// Problem constants (fixed instance)
#define RR   4
#define NN   20000
#define NSRC 20000
#define DD   256
#define EE   640000
#define KK   16
#define CAP  96

// Static scratch (allocation-free rule)
__device__ int            g_cnt[RR * NN];
__device__ unsigned short g_slots16[(size_t)RR * NN * CAP];
__device__ __half         g_H16[(size_t)NN * RR * DD];      // [N][R*D] fp16 (40MB)
__device__ __half         g_x16[(size_t)RR * NSRC * DD];    // fp16 x (40MB)

#define H2(u) (*(const __half2*)&(u))

// ---------------------------------------------------------------------------
// Fused prep, 2:1 interleave (bx%3==2 -> bucket). High per-thread MLP:
//   convert: 16 floats/thread (4 independent LDG.128 + 2 STG.128)
//   bucket : 4 edges/thread, all index loads issued before the atomic chains
// 7500 blocks total: 5000 convert (5000*256*2 uint4-groups = 2.56M),
//                    2500 bucket  (2500*256*4 edges        = 2.56M).
__global__ __launch_bounds__(256) void prep_kernel(
    const float* __restrict__ x,
    const int*   __restrict__ src_idx,
    const int*   __restrict__ dst_idx)
{
    const int bx = blockIdx.x;
    if (bx % 3 != 2) {
        int conv_id = bx - (bx + 1) / 3;                  // 0..4999
        size_t base = (size_t)conv_id * 512 + threadIdx.x; // uint4-group index
        // two groups, strided by 256 for coalescing; 4 independent loads
        float4 v0 = ((const float4*)x)[2 * base];
        float4 v1 = ((const float4*)x)[2 * base + 1];
        float4 v2 = ((const float4*)x)[2 * (base + 256)];
        float4 v3 = ((const float4*)x)[2 * (base + 256) + 1];
        __half2 h0 = __floats2half2_rn(v0.x, v0.y);
        __half2 h1 = __floats2half2_rn(v0.z, v0.w);
        __half2 h2 = __floats2half2_rn(v1.x, v1.y);
        __half2 h3 = __floats2half2_rn(v1.z, v1.w);
        uint4 pa; pa.x = *(unsigned*)&h0; pa.y = *(unsigned*)&h1;
        pa.z = *(unsigned*)&h2; pa.w = *(unsigned*)&h3;
        ((uint4*)g_x16)[base] = pa;
        __half2 h4 = __floats2half2_rn(v2.x, v2.y);
        __half2 h5 = __floats2half2_rn(v2.z, v2.w);
        __half2 h6 = __floats2half2_rn(v3.x, v3.y);
        __half2 h7 = __floats2half2_rn(v3.z, v3.w);
        uint4 pb; pb.x = *(unsigned*)&h4; pb.y = *(unsigned*)&h5;
        pb.z = *(unsigned*)&h6; pb.w = *(unsigned*)&h7;
        ((uint4*)g_x16)[base + 256] = pb;
    } else {
        int buck_id = bx / 3;                              // 0..2499
        int base = buck_id * 1024 + threadIdx.x;           // 4 edges, stride 256
        int s[4], dt[4];
        #pragma unroll
        for (int j = 0; j < 4; j++) {
            int e = base + j * 256;
            s[j]  = src_idx[e];
            dt[j] = dst_idx[e];
        }
        #pragma unroll
        for (int j = 0; j < 4; j++) {
            int e = base + j * 256;
            int r = e / EE;
            int b = r * NN + dt[j];
            int rank = atomicAdd(&g_cnt[b], 1);
            if (rank < CAP) g_slots16[(size_t)b * CAP + rank] = (unsigned short)s[j];
        }
    }
}

// ---------------------------------------------------------------------------
// One WARP per (n, r). Warp-local softmax; gather with precomputed u32 row
// offsets; 8 outstanding LDG.128 per iter, two independent 4-edge half2
// accumulator groups (fp16 chain length unchanged), fp32 flush per 8 edges.
__global__ __launch_bounds__(256) void agg_kernel(
    const float* __restrict__ d,    // [R, NSRC]
    const float* __restrict__ d1,
    const float* __restrict__ d2,
    const int*   __restrict__ split_p)
{
    const int warp = threadIdx.x >> 5;
    const int lane = threadIdx.x & 31;
    const int p = blockIdx.x * 8 + warp;
    const int n = p >> 2;
    const int g = p & 3;

    __shared__ __half2  swh[8][CAP];
    __shared__ unsigned soff[8][CAP];

    int cnt = g_cnt[g * NN + n];
    if (cnt > CAP) cnt = CAP;

    const int split = split_p ? __ldg(split_p) : 10000;
    const bool use1 = (n < split);

    const unsigned short* slot = g_slots16 + ((size_t)g * NN + n) * CAP;

    float l[3];
    int   s[3];
    #pragma unroll
    for (int j = 0; j < 3; j++) {
        int i = lane + 32 * j;
        l[j] = -1e30f; s[j] = 0;
        if (i < cnt) {
            int sv = slot[i];
            s[j] = sv;
            float dv = d[g * NSRC + sv];
            l[j] = use1 ? (d1[g * NSRC + sv] / dv)
                        : (-d2[g * NSRC + sv] / dv);
        }
    }
    float m = fmaxf(fmaxf(l[0], l[1]), l[2]);
    #pragma unroll
    for (int o = 16; o; o >>= 1) m = fmaxf(m, __shfl_xor_sync(0xffffffffu, m, o));

    float e[3];
    float sum = 0.f;
    #pragma unroll
    for (int j = 0; j < 3; j++) {
        e[j] = (lane + 32 * j < cnt) ? __expf(l[j] - m) : 0.f;
        sum += e[j];
    }
    #pragma unroll
    for (int o = 16; o; o >>= 1) sum += __shfl_xor_sync(0xffffffffu, sum, o);
    const float winv = 1.f / fmaxf(sum, 1e-9f);

    #pragma unroll
    for (int j = 0; j < 3; j++) {
        int i = lane + 32 * j;
        if (i < cnt) {
            swh[warp][i]  = __float2half2_rn(e[j] * winv);
            soff[warp][i] = (unsigned)s[j] * 32u;
        }
    }
    __syncwarp();

    const uint4* xr = (const uint4*)g_x16 + (size_t)g * NSRC * 32 + lane;
    float a0=0,a1=0,a2=0,a3=0,a4=0,a5=0,a6=0,a7=0;
    const __half2 z = __float2half2_rn(0.f);

    int i = 0;
    for (; i + 8 <= cnt; i += 8) {
        uint4 u0 = xr[soff[warp][i]];
        uint4 u1 = xr[soff[warp][i+1]];
        uint4 u2 = xr[soff[warp][i+2]];
        uint4 u3 = xr[soff[warp][i+3]];
        uint4 u4 = xr[soff[warp][i+4]];
        uint4 u5 = xr[soff[warp][i+5]];
        uint4 u6 = xr[soff[warp][i+6]];
        uint4 u7 = xr[soff[warp][i+7]];
        __half2 w0 = swh[warp][i],   w1 = swh[warp][i+1];
        __half2 w2 = swh[warp][i+2], w3 = swh[warp][i+3];
        __half2 w4 = swh[warp][i+4], w5 = swh[warp][i+5];
        __half2 w6 = swh[warp][i+6], w7 = swh[warp][i+7];
        __half2 c0 = z, c1 = z, c2 = z, c3 = z;
        __half2 e0 = z, e1 = z, e2 = z, e3 = z;
        c0 = __hfma2(w0, H2(u0.x), c0); c1 = __hfma2(w0, H2(u0.y), c1);
        c2 = __hfma2(w0, H2(u0.z), c2); c3 = __hfma2(w0, H2(u0.w), c3);
        c0 = __hfma2(w1, H2(u1.x), c0); c1 = __hfma2(w1, H2(u1.y), c1);
        c2 = __hfma2(w1, H2(u1.z), c2); c3 = __hfma2(w1, H2(u1.w), c3);
        c0 = __hfma2(w2, H2(u2.x), c0); c1 = __hfma2(w2, H2(u2.y), c1);
        c2 = __hfma2(w2, H2(u2.z), c2); c3 = __hfma2(w2, H2(u2.w), c3);
        c0 = __hfma2(w3, H2(u3.x), c0); c1 = __hfma2(w3, H2(u3.y), c1);
        c2 = __hfma2(w3, H2(u3.z), c2); c3 = __hfma2(w3, H2(u3.w), c3);
        e0 = __hfma2(w4, H2(u4.x), e0); e1 = __hfma2(w4, H2(u4.y), e1);
        e2 = __hfma2(w4, H2(u4.z), e2); e3 = __hfma2(w4, H2(u4.w), e3);
        e0 = __hfma2(w5, H2(u5.x), e0); e1 = __hfma2(w5, H2(u5.y), e1);
        e2 = __hfma2(w5, H2(u5.z), e2); e3 = __hfma2(w5, H2(u5.w), e3);
        e0 = __hfma2(w6, H2(u6.x), e0); e1 = __hfma2(w6, H2(u6.y), e1);
        e2 = __hfma2(w6, H2(u6.z), e2); e3 = __hfma2(w6, H2(u6.w), e3);
        e0 = __hfma2(w7, H2(u7.x), e0); e1 = __hfma2(w7, H2(u7.y), e1);
        e2 = __hfma2(w7, H2(u7.z), e2); e3 = __hfma2(w7, H2(u7.w), e3);
        float2 f0 = __half22float2(c0), f1 = __half22float2(c1);
        float2 f2 = __half22float2(c2), f3 = __half22float2(c3);
        float2 g0 = __half22float2(e0), g1 = __half22float2(e1);
        float2 g2 = __half22float2(e2), g3 = __half22float2(e3);
        a0 += f0.x + g0.x; a1 += f0.y + g0.y;
        a2 += f1.x + g1.x; a3 += f1.y + g1.y;
        a4 += f2.x + g2.x; a5 += f2.y + g2.y;
        a6 += f3.x + g3.x; a7 += f3.y + g3.y;
    }
    for (; i + 4 <= cnt; i += 4) {
        __half2 w0 = swh[warp][i],   w1 = swh[warp][i+1];
        __half2 w2 = swh[warp][i+2], w3 = swh[warp][i+3];
        uint4 u0 = xr[soff[warp][i]];
        uint4 u1 = xr[soff[warp][i+1]];
        uint4 u2 = xr[soff[warp][i+2]];
        uint4 u3 = xr[soff[warp][i+3]];
        __half2 c0 = z, c1 = z, c2 = z, c3 = z;
        c0 = __hfma2(w0, H2(u0.x), c0); c1 = __hfma2(w0, H2(u0.y), c1);
        c2 = __hfma2(w0, H2(u0.z), c2); c3 = __hfma2(w0, H2(u0.w), c3);
        c0 = __hfma2(w1, H2(u1.x), c0); c1 = __hfma2(w1, H2(u1.y), c1);
        c2 = __hfma2(w1, H2(u1.z), c2); c3 = __hfma2(w1, H2(u1.w), c3);
        c0 = __hfma2(w2, H2(u2.x), c0); c1 = __hfma2(w2, H2(u2.y), c1);
        c2 = __hfma2(w2, H2(u2.z), c2); c3 = __hfma2(w2, H2(u2.w), c3);
        c0 = __hfma2(w3, H2(u3.x), c0); c1 = __hfma2(w3, H2(u3.y), c1);
        c2 = __hfma2(w3, H2(u3.z), c2); c3 = __hfma2(w3, H2(u3.w), c3);
        float2 f0 = __half22float2(c0), f1 = __half22float2(c1);
        float2 f2 = __half22float2(c2), f3 = __half22float2(c3);
        a0 += f0.x; a1 += f0.y; a2 += f1.x; a3 += f1.y;
        a4 += f2.x; a5 += f2.y; a6 += f3.x; a7 += f3.y;
    }
    for (; i < cnt; i++) {
        __half2 w0 = swh[warp][i];
        uint4 u0 = xr[soff[warp][i]];
        float2 f0 = __half22float2(__hmul2(w0, H2(u0.x)));
        float2 f1 = __half22float2(__hmul2(w0, H2(u0.y)));
        float2 f2 = __half22float2(__hmul2(w0, H2(u0.z)));
        float2 f3 = __half22float2(__hmul2(w0, H2(u0.w)));
        a0 += f0.x; a1 += f0.y; a2 += f1.x; a3 += f1.y;
        a4 += f2.x; a5 += f2.y; a6 += f3.x; a7 += f3.y;
    }

    __half2 h0 = __floats2half2_rn(a0, a1);
    __half2 h1 = __floats2half2_rn(a2, a3);
    __half2 h2 = __floats2half2_rn(a4, a5);
    __half2 h3 = __floats2half2_rn(a6, a7);
    uint4 packed;
    packed.x = *(const unsigned*)&h0;
    packed.y = *(const unsigned*)&h1;
    packed.z = *(const unsigned*)&h2;
    packed.w = *(const unsigned*)&h3;
    ((uint4*)(g_H16 + ((size_t)n * RR + g) * DD))[lane] = packed;
}

// ---------------------------------------------------------------------------
// One block per node. Thread t owns 4 elems (uint2). Squared diffs in regs as
// half2; s-accum in half2 split partials merged in fp32. 32-bit H indexing.
__global__ __launch_bounds__(256) void mask_kernel(
    const int* __restrict__ cand,   // [N, K]
    float*     __restrict__ out)    // [N, D]
{
    const int n = blockIdx.x;
    const int t = threadIdx.x;
    const int lane = t & 31, w = t >> 5;

    __shared__ unsigned coff[KK];
    __shared__ __half   wsumh[8][KK];
    __shared__ __half2  satth[KK];
    __shared__ float    sval[RR * DD];

    if (t < KK) coff[t] = (unsigned)cand[n * KK + t] * 256u;
    __syncthreads();

    const uint2* Hb = (const uint2*)g_H16 + t;
    const uint2 ownu = Hb[(unsigned)n * 256u];
    const __half2 own0 = H2(ownu.x);
    const __half2 own1 = H2(ownu.y);

    __half2 sq0[KK], sq1[KK];
    __half2 ph[KK];
    #pragma unroll
    for (int k = 0; k < KK; k++) {
        uint2 cu = Hb[coff[k]];
        __half2 d0 = __hsub2(own0, H2(cu.x));
        __half2 d1 = __hsub2(own1, H2(cu.y));
        __half2 q0 = __hmul2(d0, d0);
        __half2 q1 = __hmul2(d1, d1);
        sq0[k] = q0; sq1[k] = q1;
        ph[k] = __hadd2(q0, q1);
    }

    __half2 pp[KK / 2];
    #pragma unroll
    for (int j = 0; j < KK / 2; j++) {
        __half a = __hadd(__low2half(ph[2*j]),     __high2half(ph[2*j]));
        __half b = __hadd(__low2half(ph[2*j + 1]), __high2half(ph[2*j + 1]));
        pp[j] = __halves2half2(a, b);
    }
    #pragma unroll
    for (int j = 0; j < KK / 2; j++) {
        unsigned v = *(unsigned*)&pp[j];
        #pragma unroll
        for (int o = 16; o; o >>= 1) {
            unsigned u = __shfl_xor_sync(0xffffffffu, v, o);
            __half2 hv = __hadd2(*(__half2*)&v, *(__half2*)&u);
            v = *(unsigned*)&hv;
        }
        if (lane == 0) ((__half2*)&wsumh[w][0])[j] = *(__half2*)&v;
    }
    __syncthreads();

    if (t < 32) {
        float dist = 1e30f;
        if (t < KK) {
            float s = 0.f;
            #pragma unroll
            for (int ww = 0; ww < 8; ww++) s += __half2float(wsumh[ww][t]);
            dist = sqrtf(s);
        }
        float mn = dist;
        #pragma unroll
        for (int o = 16; o; o >>= 1) mn = fminf(mn, __shfl_xor_sync(0xffffffffu, mn, o));
        float e = (t < KK) ? __expf(mn - dist) : 0.f;
        float s = e;
        #pragma unroll
        for (int o = 16; o; o >>= 1) s += __shfl_xor_sync(0xffffffffu, s, o);
        if (t < KK) satth[t] = __float2half2_rn(e / s);
    }
    __syncthreads();

    const __half2 z = __float2half2_rn(0.f);
    __half2 pa0 = z, pa1 = z, pb0 = z, pb1 = z;
    #pragma unroll
    for (int k = 0; k < 8; k++) {
        __half2 a = satth[k];
        pa0 = __hfma2(a, sq0[k], pa0);
        pa1 = __hfma2(a, sq1[k], pa1);
    }
    #pragma unroll
    for (int k = 8; k < KK; k++) {
        __half2 a = satth[k];
        pb0 = __hfma2(a, sq0[k], pb0);
        pb1 = __hfma2(a, sq1[k], pb1);
    }
    float2 fa0 = __half22float2(pa0), fb0 = __half22float2(pb0);
    float2 fa1 = __half22float2(pa1), fb1 = __half22float2(pb1);
    float sx = fa0.x + fb0.x, sy = fa0.y + fb0.y;
    float sz = fa1.x + fb1.x, sw_ = fa1.y + fb1.y;

    float2 o0 = __half22float2(own0);
    float2 o1 = __half22float2(own1);
    float4 val;
    val.x = o0.x * __expf(-sx);
    val.y = o0.y * __expf(-sy);
    val.z = o1.x * __expf(-sz);
    val.w = o1.y * __expf(-sw_);
    ((float4*)sval)[t] = val;
    __syncthreads();

    if (t < 64) {
        float4 b0 = ((float4*)sval)[t];
        float4 b1 = ((float4*)sval)[t + 64];
        float4 b2 = ((float4*)sval)[t + 128];
        float4 b3 = ((float4*)sval)[t + 192];
        float4 o;
        o.x = b0.x + b1.x + b2.x + b3.x;
        o.y = b0.y + b1.y + b2.y + b3.y;
        o.z = b0.z + b1.z + b2.z + b3.z;
        o.w = b0.w + b1.w + b2.w + b3.w;
        ((float4*)(out + (size_t)n * DD))[t] = o;
    }
}

// ---------------------------------------------------------------------------
extern "C" void kernel_launch(void* const* d_in, const int* in_sizes, int n_in,
                              void* d_out, int out_size)
{
    const float* x    = (const float*)d_in[0];
    const float* d    = (const float*)d_in[1];
    const float* d1   = (const float*)d_in[2];
    const float* d2   = (const float*)d_in[3];
    const int*   src  = (const int*)d_in[4];
    const int*   dst  = (const int*)d_in[5];
    const int*   cand = (const int*)d_in[6];
    const int*   split = (n_in >= 8) ? (const int*)d_in[7] : nullptr;
    float* out = (float*)d_out;

    (void)in_sizes; (void)out_size;

    static void* cnt_ptr = nullptr;
    if (cnt_ptr == nullptr) cudaGetSymbolAddress(&cnt_ptr, g_cnt);

    cudaMemsetAsync(cnt_ptr, 0, (size_t)RR * NN * sizeof(int), 0);
    prep_kernel<<<7500, 256>>>(x, src, dst);
    agg_kernel<<<(RR * NN) / 8, 256>>>(d, d1, d2, split);
    mask_kernel<<<NN, 256>>>(cand, out);
}

// round 9
// speedup vs baseline: 2.3718x; 1.0090x over previous
#include <cuda_runtime.h>
#include <cuda_fp16.h>
#include <math.h>

// Problem constants (fixed instance)
#define RR   4
#define NN   20000
#define NSRC 20000
#define DD   256
#define EE   640000
#define KK   16
#define SUBS 4         // sub-buckets per (r,dst) to cut atomic contention
#define SCAP 32        // capacity per sub-bucket (Poisson(8) tail ~1e-12)
#define CAPT (SUBS * SCAP)   // 128 logical slots per (r,dst)

// Static scratch (allocation-free rule)
__device__ int            g_cnt4[RR * NN * SUBS];                    // 1.25MB
__device__ unsigned short g_slots16[(size_t)RR * NN * CAPT];         // 20MB
__device__ __half         g_H16[(size_t)NN * RR * DD];               // 40MB
__device__ __half         g_x16[(size_t)RR * NSRC * DD];             // 40MB

#define H2(u) (*(const __half2*)&(u))

// ---------------------------------------------------------------------------
// Fused prep, 2:1 interleave (bx%3==2 -> bucket).
//   convert: 16 floats/thread (4 LDG.128 + 2 STG.128)
//   bucket : 4 edges/thread into 4-way sub-buckets (e&3) -> 4x less contention
__global__ __launch_bounds__(256) void prep_kernel(
    const float* __restrict__ x,
    const int*   __restrict__ src_idx,
    const int*   __restrict__ dst_idx)
{
    const int bx = blockIdx.x;
    if (bx % 3 != 2) {
        int conv_id = bx - (bx + 1) / 3;                   // 0..4999
        size_t base = (size_t)conv_id * 512 + threadIdx.x; // uint4-group index
        float4 v0 = ((const float4*)x)[2 * base];
        float4 v1 = ((const float4*)x)[2 * base + 1];
        float4 v2 = ((const float4*)x)[2 * (base + 256)];
        float4 v3 = ((const float4*)x)[2 * (base + 256) + 1];
        __half2 h0 = __floats2half2_rn(v0.x, v0.y);
        __half2 h1 = __floats2half2_rn(v0.z, v0.w);
        __half2 h2 = __floats2half2_rn(v1.x, v1.y);
        __half2 h3 = __floats2half2_rn(v1.z, v1.w);
        uint4 pa; pa.x = *(unsigned*)&h0; pa.y = *(unsigned*)&h1;
        pa.z = *(unsigned*)&h2; pa.w = *(unsigned*)&h3;
        ((uint4*)g_x16)[base] = pa;
        __half2 h4 = __floats2half2_rn(v2.x, v2.y);
        __half2 h5 = __floats2half2_rn(v2.z, v2.w);
        __half2 h6 = __floats2half2_rn(v3.x, v3.y);
        __half2 h7 = __floats2half2_rn(v3.z, v3.w);
        uint4 pb; pb.x = *(unsigned*)&h4; pb.y = *(unsigned*)&h5;
        pb.z = *(unsigned*)&h6; pb.w = *(unsigned*)&h7;
        ((uint4*)g_x16)[base + 256] = pb;
    } else {
        int buck_id = bx / 3;                              // 0..2499
        int base = buck_id * 1024 + threadIdx.x;           // 4 edges, stride 256
        int s[4], dt[4];
        #pragma unroll
        for (int j = 0; j < 4; j++) {
            int e = base + j * 256;
            s[j]  = src_idx[e];
            dt[j] = dst_idx[e];
        }
        #pragma unroll
        for (int j = 0; j < 4; j++) {
            int e = base + j * 256;
            int r = e / EE;
            int sub = e & (SUBS - 1);
            int b4 = (r * NN + dt[j]) * SUBS + sub;
            int rank = atomicAdd(&g_cnt4[b4], 1);
            if (rank < SCAP)
                g_slots16[(size_t)b4 * SCAP + rank] = (unsigned short)s[j];
        }
    }
}

// ---------------------------------------------------------------------------
// One WARP per (n, r). Reads 4 sub-bucket counters as int4, maps logical slot
// index -> (sub, rank) via prefix compares. Warp softmax, then 8-wide uint4
// fp16 gather with two independent half2 accumulator groups.
__global__ __launch_bounds__(256) void agg_kernel(
    const float* __restrict__ d,    // [R, NSRC]
    const float* __restrict__ d1,
    const float* __restrict__ d2,
    const int*   __restrict__ split_p)
{
    const int warp = threadIdx.x >> 5;
    const int lane = threadIdx.x & 31;
    const int p = blockIdx.x * 8 + warp;
    const int n = p >> 2;
    const int g = p & 3;

    __shared__ __half2  swh[8][CAPT];
    __shared__ unsigned soff[8][CAPT];

    const int b = g * NN + n;
    int4 c4 = ((const int4*)g_cnt4)[b];
    int c0 = min(c4.x, SCAP), c1 = min(c4.y, SCAP);
    int c2 = min(c4.z, SCAP), c3 = min(c4.w, SCAP);
    const int pre1 = c0, pre2 = c0 + c1, pre3 = c0 + c1 + c2;
    const int cnt  = pre3 + c3;

    const int split = split_p ? __ldg(split_p) : 10000;
    const bool use1 = (n < split);

    const unsigned short* slot = g_slots16 + (size_t)b * CAPT;

    float l[4];
    int   s[4];
    #pragma unroll
    for (int j = 0; j < 4; j++) {
        int i = lane + 32 * j;
        l[j] = -1e30f; s[j] = 0;
        if (i < cnt) {
            int sub  = (i >= pre1) + (i >= pre2) + (i >= pre3);
            int base = (sub == 0) ? 0 : ((sub == 1) ? pre1 : ((sub == 2) ? pre2 : pre3));
            int sv = slot[sub * SCAP + (i - base)];
            s[j] = sv;
            float dv = d[g * NSRC + sv];
            l[j] = use1 ? (d1[g * NSRC + sv] / dv)
                        : (-d2[g * NSRC + sv] / dv);
        }
    }
    float m = fmaxf(fmaxf(l[0], l[1]), fmaxf(l[2], l[3]));
    #pragma unroll
    for (int o = 16; o; o >>= 1) m = fmaxf(m, __shfl_xor_sync(0xffffffffu, m, o));

    float e[4];
    float sum = 0.f;
    #pragma unroll
    for (int j = 0; j < 4; j++) {
        e[j] = (lane + 32 * j < cnt) ? __expf(l[j] - m) : 0.f;
        sum += e[j];
    }
    #pragma unroll
    for (int o = 16; o; o >>= 1) sum += __shfl_xor_sync(0xffffffffu, sum, o);
    const float winv = 1.f / fmaxf(sum, 1e-9f);

    #pragma unroll
    for (int j = 0; j < 4; j++) {
        int i = lane + 32 * j;
        if (i < cnt) {
            swh[warp][i]  = __float2half2_rn(e[j] * winv);
            soff[warp][i] = (unsigned)s[j] * 32u;
        }
    }
    __syncwarp();

    const uint4* xr = (const uint4*)g_x16 + (size_t)g * NSRC * 32 + lane;
    float a0=0,a1=0,a2=0,a3=0,a4=0,a5=0,a6=0,a7=0;
    const __half2 z = __float2half2_rn(0.f);

    int i = 0;
    for (; i + 8 <= cnt; i += 8) {
        uint4 u0 = xr[soff[warp][i]];
        uint4 u1 = xr[soff[warp][i+1]];
        uint4 u2 = xr[soff[warp][i+2]];
        uint4 u3 = xr[soff[warp][i+3]];
        uint4 u4 = xr[soff[warp][i+4]];
        uint4 u5 = xr[soff[warp][i+5]];
        uint4 u6 = xr[soff[warp][i+6]];
        uint4 u7 = xr[soff[warp][i+7]];
        __half2 w0 = swh[warp][i],   w1 = swh[warp][i+1];
        __half2 w2 = swh[warp][i+2], w3 = swh[warp][i+3];
        __half2 w4 = swh[warp][i+4], w5 = swh[warp][i+5];
        __half2 w6 = swh[warp][i+6], w7 = swh[warp][i+7];
        __half2 c0h = z, c1h = z, c2h = z, c3h = z;
        __half2 e0h = z, e1h = z, e2h = z, e3h = z;
        c0h = __hfma2(w0, H2(u0.x), c0h); c1h = __hfma2(w0, H2(u0.y), c1h);
        c2h = __hfma2(w0, H2(u0.z), c2h); c3h = __hfma2(w0, H2(u0.w), c3h);
        c0h = __hfma2(w1, H2(u1.x), c0h); c1h = __hfma2(w1, H2(u1.y), c1h);
        c2h = __hfma2(w1, H2(u1.z), c2h); c3h = __hfma2(w1, H2(u1.w), c3h);
        c0h = __hfma2(w2, H2(u2.x), c0h); c1h = __hfma2(w2, H2(u2.y), c1h);
        c2h = __hfma2(w2, H2(u2.z), c2h); c3h = __hfma2(w2, H2(u2.w), c3h);
        c0h = __hfma2(w3, H2(u3.x), c0h); c1h = __hfma2(w3, H2(u3.y), c1h);
        c2h = __hfma2(w3, H2(u3.z), c2h); c3h = __hfma2(w3, H2(u3.w), c3h);
        e0h = __hfma2(w4, H2(u4.x), e0h); e1h = __hfma2(w4, H2(u4.y), e1h);
        e2h = __hfma2(w4, H2(u4.z), e2h); e3h = __hfma2(w4, H2(u4.w), e3h);
        e0h = __hfma2(w5, H2(u5.x), e0h); e1h = __hfma2(w5, H2(u5.y), e1h);
        e2h = __hfma2(w5, H2(u5.z), e2h); e3h = __hfma2(w5, H2(u5.w), e3h);
        e0h = __hfma2(w6, H2(u6.x), e0h); e1h = __hfma2(w6, H2(u6.y), e1h);
        e2h = __hfma2(w6, H2(u6.z), e2h); e3h = __hfma2(w6, H2(u6.w), e3h);
        e0h = __hfma2(w7, H2(u7.x), e0h); e1h = __hfma2(w7, H2(u7.y), e1h);
        e2h = __hfma2(w7, H2(u7.z), e2h); e3h = __hfma2(w7, H2(u7.w), e3h);
        float2 f0 = __half22float2(c0h), f1 = __half22float2(c1h);
        float2 f2 = __half22float2(c2h), f3 = __half22float2(c3h);
        float2 g0 = __half22float2(e0h), g1 = __half22float2(e1h);
        float2 g2 = __half22float2(e2h), g3 = __half22float2(e3h);
        a0 += f0.x + g0.x; a1 += f0.y + g0.y;
        a2 += f1.x + g1.x; a3 += f1.y + g1.y;
        a4 += f2.x + g2.x; a5 += f2.y + g2.y;
        a6 += f3.x + g3.x; a7 += f3.y + g3.y;
    }
    for (; i + 4 <= cnt; i += 4) {
        __half2 w0 = swh[warp][i],   w1 = swh[warp][i+1];
        __half2 w2 = swh[warp][i+2], w3 = swh[warp][i+3];
        uint4 u0 = xr[soff[warp][i]];
        uint4 u1 = xr[soff[warp][i+1]];
        uint4 u2 = xr[soff[warp][i+2]];
        uint4 u3 = xr[soff[warp][i+3]];
        __half2 c0h = z, c1h = z, c2h = z, c3h = z;
        c0h = __hfma2(w0, H2(u0.x), c0h); c1h = __hfma2(w0, H2(u0.y), c1h);
        c2h = __hfma2(w0, H2(u0.z), c2h); c3h = __hfma2(w0, H2(u0.w), c3h);
        c0h = __hfma2(w1, H2(u1.x), c0h); c1h = __hfma2(w1, H2(u1.y), c1h);
        c2h = __hfma2(w1, H2(u1.z), c2h); c3h = __hfma2(w1, H2(u1.w), c3h);
        c0h = __hfma2(w2, H2(u2.x), c0h); c1h = __hfma2(w2, H2(u2.y), c1h);
        c2h = __hfma2(w2, H2(u2.z), c2h); c3h = __hfma2(w2, H2(u2.w), c3h);
        c0h = __hfma2(w3, H2(u3.x), c0h); c1h = __hfma2(w3, H2(u3.y), c1h);
        c2h = __hfma2(w3, H2(u3.z), c2h); c3h = __hfma2(w3, H2(u3.w), c3h);
        float2 f0 = __half22float2(c0h), f1 = __half22float2(c1h);
        float2 f2 = __half22float2(c2h), f3 = __half22float2(c3h);
        a0 += f0.x; a1 += f0.y; a2 += f1.x; a3 += f1.y;
        a4 += f2.x; a5 += f2.y; a6 += f3.x; a7 += f3.y;
    }
    for (; i < cnt; i++) {
        __half2 w0 = swh[warp][i];
        uint4 u0 = xr[soff[warp][i]];
        float2 f0 = __half22float2(__hmul2(w0, H2(u0.x)));
        float2 f1 = __half22float2(__hmul2(w0, H2(u0.y)));
        float2 f2 = __half22float2(__hmul2(w0, H2(u0.z)));
        float2 f3 = __half22float2(__hmul2(w0, H2(u0.w)));
        a0 += f0.x; a1 += f0.y; a2 += f1.x; a3 += f1.y;
        a4 += f2.x; a5 += f2.y; a6 += f3.x; a7 += f3.y;
    }

    __half2 h0 = __floats2half2_rn(a0, a1);
    __half2 h1 = __floats2half2_rn(a2, a3);
    __half2 h2 = __floats2half2_rn(a4, a5);
    __half2 h3 = __floats2half2_rn(a6, a7);
    uint4 packed;
    packed.x = *(const unsigned*)&h0;
    packed.y = *(const unsigned*)&h1;
    packed.z = *(const unsigned*)&h2;
    packed.w = *(const unsigned*)&h3;
    ((uint4*)(g_H16 + ((size_t)n * RR + g) * DD))[lane] = packed;
}

// ---------------------------------------------------------------------------
// One block per node. Thread t owns 4 elems (uint2). Squared diffs in regs as
// half2; s-accum in half2 split partials merged in fp32. 32-bit H indexing.
__global__ __launch_bounds__(256) void mask_kernel(
    const int* __restrict__ cand,   // [N, K]
    float*     __restrict__ out)    // [N, D]
{
    const int n = blockIdx.x;
    const int t = threadIdx.x;
    const int lane = t & 31, w = t >> 5;

    __shared__ unsigned coff[KK];
    __shared__ __half   wsumh[8][KK];
    __shared__ __half2  satth[KK];
    __shared__ float    sval[RR * DD];

    if (t < KK) coff[t] = (unsigned)cand[n * KK + t] * 256u;
    __syncthreads();

    const uint2* Hb = (const uint2*)g_H16 + t;
    const uint2 ownu = Hb[(unsigned)n * 256u];
    const __half2 own0 = H2(ownu.x);
    const __half2 own1 = H2(ownu.y);

    __half2 sq0[KK], sq1[KK];
    __half2 ph[KK];
    #pragma unroll
    for (int k = 0; k < KK; k++) {
        uint2 cu = Hb[coff[k]];
        __half2 d0 = __hsub2(own0, H2(cu.x));
        __half2 d1 = __hsub2(own1, H2(cu.y));
        __half2 q0 = __hmul2(d0, d0);
        __half2 q1 = __hmul2(d1, d1);
        sq0[k] = q0; sq1[k] = q1;
        ph[k] = __hadd2(q0, q1);
    }

    __half2 pp[KK / 2];
    #pragma unroll
    for (int j = 0; j < KK / 2; j++) {
        __half a = __hadd(__low2half(ph[2*j]),     __high2half(ph[2*j]));
        __half b = __hadd(__low2half(ph[2*j + 1]), __high2half(ph[2*j + 1]));
        pp[j] = __halves2half2(a, b);
    }
    #pragma unroll
    for (int j = 0; j < KK / 2; j++) {
        unsigned v = *(unsigned*)&pp[j];
        #pragma unroll
        for (int o = 16; o; o >>= 1) {
            unsigned u = __shfl_xor_sync(0xffffffffu, v, o);
            __half2 hv = __hadd2(*(__half2*)&v, *(__half2*)&u);
            v = *(unsigned*)&hv;
        }
        if (lane == 0) ((__half2*)&wsumh[w][0])[j] = *(__half2*)&v;
    }
    __syncthreads();

    if (t < 32) {
        float dist = 1e30f;
        if (t < KK) {
            float s = 0.f;
            #pragma unroll
            for (int ww = 0; ww < 8; ww++) s += __half2float(wsumh[ww][t]);
            dist = sqrtf(s);
        }
        float mn = dist;
        #pragma unroll
        for (int o = 16; o; o >>= 1) mn = fminf(mn, __shfl_xor_sync(0xffffffffu, mn, o));
        float e = (t < KK) ? __expf(mn - dist) : 0.f;
        float s = e;
        #pragma unroll
        for (int o = 16; o; o >>= 1) s += __shfl_xor_sync(0xffffffffu, s, o);
        if (t < KK) satth[t] = __float2half2_rn(e / s);
    }
    __syncthreads();

    const __half2 z = __float2half2_rn(0.f);
    __half2 pa0 = z, pa1 = z, pb0 = z, pb1 = z;
    #pragma unroll
    for (int k = 0; k < 8; k++) {
        __half2 a = satth[k];
        pa0 = __hfma2(a, sq0[k], pa0);
        pa1 = __hfma2(a, sq1[k], pa1);
    }
    #pragma unroll
    for (int k = 8; k < KK; k++) {
        __half2 a = satth[k];
        pb0 = __hfma2(a, sq0[k], pb0);
        pb1 = __hfma2(a, sq1[k], pb1);
    }
    float2 fa0 = __half22float2(pa0), fb0 = __half22float2(pb0);
    float2 fa1 = __half22float2(pa1), fb1 = __half22float2(pb1);
    float sx = fa0.x + fb0.x, sy = fa0.y + fb0.y;
    float sz = fa1.x + fb1.x, sw_ = fa1.y + fb1.y;

    float2 o0 = __half22float2(own0);
    float2 o1 = __half22float2(own1);
    float4 val;
    val.x = o0.x * __expf(-sx);
    val.y = o0.y * __expf(-sy);
    val.z = o1.x * __expf(-sz);
    val.w = o1.y * __expf(-sw_);
    ((float4*)sval)[t] = val;
    __syncthreads();

    if (t < 64) {
        float4 b0 = ((float4*)sval)[t];
        float4 b1 = ((float4*)sval)[t + 64];
        float4 b2 = ((float4*)sval)[t + 128];
        float4 b3 = ((float4*)sval)[t + 192];
        float4 o;
        o.x = b0.x + b1.x + b2.x + b3.x;
        o.y = b0.y + b1.y + b2.y + b3.y;
        o.z = b0.z + b1.z + b2.z + b3.z;
        o.w = b0.w + b1.w + b2.w + b3.w;
        ((float4*)(out + (size_t)n * DD))[t] = o;
    }
}

// ---------------------------------------------------------------------------
extern "C" void kernel_launch(void* const* d_in, const int* in_sizes, int n_in,
                              void* d_out, int out_size)
{
    const float* x    = (const float*)d_in[0];
    const float* d    = (const float*)d_in[1];
    const float* d1   = (const float*)d_in[2];
    const float* d2   = (const float*)d_in[3];
    const int*   src  = (const int*)d_in[4];
    const int*   dst  = (const int*)d_in[5];
    const int*   cand = (const int*)d_in[6];
    const int*   split = (n_in >= 8) ? (const int*)d_in[7] : nullptr;
    float* out = (float*)d_out;

    (void)in_sizes; (void)out_size;

    static void* cnt_ptr = nullptr;
    if (cnt_ptr == nullptr) cudaGetSymbolAddress(&cnt_ptr, g_cnt4);

    cudaMemsetAsync(cnt_ptr, 0, (size_t)RR * NN * SUBS * sizeof(int), 0);
    prep_kernel<<<7500, 256>>>(x, src, dst);
    agg_kernel<<<(RR * NN) / 8, 256>>>(d, d1, d2, split);
    mask_kernel<<<NN, 256>>>(cand, out);
}